// round 1
// baseline (speedup 1.0000x reference)
#include <cuda_runtime.h>
#include <cuda_bf16.h>
#include <math.h>

// Problem constants
#define B_   256
#define T_   192
#define F_   8
#define E0_  32
#define E1_  16
#define DIN_ 56
#define H_   512
#define G4_  2048
#define BT_  (B_ * T_)      // 49152
#define KC   32             // K-chunk for smem staging

// ---------------- scratch (static device arrays; no allocation) ----------------
__device__ float g_x [BT_ * DIN_];            // 11 MB  : concat(x_cont, emb0, emb1)
__device__ float g_xz[(size_t)BT_ * G4_];     // 402 MB : precomputed input projection (+bias)
__device__ float g_hs[(size_t)BT_ * H_];      // 100 MB : per-step hidden outputs of current layer
__device__ float g_h0[B_ * H_];               // ping-pong h state
__device__ float g_h1[B_ * H_];
__device__ float g_c [B_ * H_];               // cell state (in-place)

// ---------------- helpers ----------------
__device__ __forceinline__ unsigned f2tf(float x) {
    unsigned r;
    asm("cvt.rna.tf32.f32 %0, %1;" : "=r"(r) : "f"(x));
    return r;
}

__device__ __forceinline__ void mma8(float* c,
                                     unsigned a0, unsigned a1, unsigned a2, unsigned a3,
                                     unsigned b0, unsigned b1) {
    asm volatile(
        "mma.sync.aligned.m16n8k8.row.col.f32.tf32.tf32.f32 "
        "{%0,%1,%2,%3},{%4,%5,%6,%7},{%8,%9},{%0,%1,%2,%3};\n"
        : "+f"(c[0]), "+f"(c[1]), "+f"(c[2]), "+f"(c[3])
        : "r"(a0), "r"(a1), "r"(a2), "r"(a3), "r"(b0), "r"(b1));
}

__device__ __forceinline__ float sigm(float x) { return 1.0f / (1.0f + expf(-x)); }

// ---------------- tiny kernels ----------------
__global__ void k_zero(float* a, float* b, int n) {
    int i = blockIdx.x * blockDim.x + threadIdx.x;
    if (i < n) { a[i] = 0.0f; b[i] = 0.0f; }
}

__global__ void k_build_x(const float* __restrict__ xc,
                          const int* __restrict__ c0, const int* __restrict__ c1,
                          const float* __restrict__ e0, const float* __restrict__ e1) {
    int i = blockIdx.x * blockDim.x + threadIdx.x;
    if (i >= BT_ * DIN_) return;
    int bt = i / DIN_;
    int d  = i - bt * DIN_;
    float v;
    if (d < F_)              v = xc[bt * F_ + d];
    else if (d < F_ + E0_)   v = e0[c0[bt] * E0_ + (d - F_)];
    else                     v = e1[c1[bt] * E1_ + (d - F_ - E0_)];
    g_x[i] = v;
}

// ---------------- generic TF32 GEMM: C[M,2048] = A[M,K] @ W[K,2048] + bias ----------------
// CTA tile 64x64, 256 threads = 8 warps arranged 4(M) x 2(N). Warp tile 16x32.
__global__ void __launch_bounds__(256)
k_gemm(const float* __restrict__ A, int lda, int K,
       const float* __restrict__ W, const float* __restrict__ bias,
       float* __restrict__ C) {
    __shared__ unsigned As[64][KC + 1];
    __shared__ unsigned Bs[KC][64 + 4];
    int m0 = blockIdx.x * 64, n0 = blockIdx.y * 64;
    int tid = threadIdx.x;
    int lane = tid & 31, warp = tid >> 5;
    int wm = warp >> 1, wn = warp & 1;
    int g = lane >> 2, tg = lane & 3;

    float acc[4][4];
#pragma unroll
    for (int i = 0; i < 4; i++)
#pragma unroll
        for (int j = 0; j < 4; j++) acc[i][j] = 0.0f;

    for (int k0 = 0; k0 < K; k0 += KC) {
        for (int i = tid; i < 64 * KC; i += 256) {
            int r = i >> 5, kk = i & 31;
            int kg = k0 + kk;
            As[r][kk] = f2tf((kg < K) ? A[(size_t)(m0 + r) * lda + kg] : 0.0f);
        }
        for (int i = tid; i < KC * 64; i += 256) {
            int kk = i >> 6, c = i & 63;
            int kg = k0 + kk;
            Bs[kk][c] = f2tf((kg < K) ? W[(size_t)kg * G4_ + n0 + c] : 0.0f);
        }
        __syncthreads();
#pragma unroll
        for (int ks = 0; ks < KC; ks += 8) {
            unsigned a0 = As[wm * 16 + g][ks + tg];
            unsigned a1 = As[wm * 16 + g + 8][ks + tg];
            unsigned a2 = As[wm * 16 + g][ks + tg + 4];
            unsigned a3 = As[wm * 16 + g + 8][ks + tg + 4];
#pragma unroll
            for (int nt = 0; nt < 4; nt++) {
                unsigned b0 = Bs[ks + tg][wn * 32 + nt * 8 + g];
                unsigned b1 = Bs[ks + tg + 4][wn * 32 + nt * 8 + g];
                mma8(acc[nt], a0, a1, a2, a3, b0, b1);
            }
        }
        __syncthreads();
    }

    int rl = wm * 16 + g;
#pragma unroll
    for (int nt = 0; nt < 4; nt++) {
        int cl  = wn * 32 + nt * 8 + tg * 2;
        int col = n0 + cl;
        float bb0 = bias[col], bb1 = bias[col + 1];
        size_t o0 = (size_t)(m0 + rl) * G4_ + col;
        size_t o1 = (size_t)(m0 + rl + 8) * G4_ + col;
        C[o0]     = acc[nt][0] + bb0;
        C[o0 + 1] = acc[nt][1] + bb1;
        C[o1]     = acc[nt][2] + bb0;
        C[o1 + 1] = acc[nt][3] + bb1;
    }
}

// ---------------- fused LSTM step ----------------
// z[b, :] = xz[b*T + t, :] + h_in[b, :] @ Wr ; gates ; update c (in place), h_out, hs.
// CTA owns 64 batch rows x 16 hidden cols; computes the 4 gate columns for them
// (z cols j, 512+j, 1024+j, 1536+j) so the cell update is CTA-local.
// grid = (B/64, H/16) = (4, 32)
__global__ void __launch_bounds__(256)
k_step(const float* __restrict__ Wr, const float* __restrict__ xz, int t,
       const float* __restrict__ hin, float* __restrict__ hout,
       float* __restrict__ cst, float* __restrict__ hs) {
    __shared__ unsigned As[64][KC + 1];
    __shared__ unsigned Bs[KC][64 + 4];
    __shared__ float    zs[64][68];
    int m0 = blockIdx.x * 64;
    int j0 = blockIdx.y * 16;
    int tid = threadIdx.x;
    int lane = tid & 31, warp = tid >> 5;
    int wm = warp >> 1, wn = warp & 1;
    int g = lane >> 2, tg = lane & 3;

    float acc[4][4];
#pragma unroll
    for (int i = 0; i < 4; i++)
#pragma unroll
        for (int j = 0; j < 4; j++) acc[i][j] = 0.0f;

    for (int k0 = 0; k0 < H_; k0 += KC) {
        for (int i = tid; i < 64 * KC; i += 256) {
            int r = i >> 5, kk = i & 31;
            As[r][kk] = f2tf(hin[(m0 + r) * H_ + k0 + kk]);
        }
        for (int i = tid; i < KC * 64; i += 256) {
            int kk = i >> 6, c = i & 63;
            int col = ((c >> 4) << 9) + j0 + (c & 15);   // gate*512 + j0 + j
            Bs[kk][c] = f2tf(Wr[(size_t)(k0 + kk) * G4_ + col]);
        }
        __syncthreads();
#pragma unroll
        for (int ks = 0; ks < KC; ks += 8) {
            unsigned a0 = As[wm * 16 + g][ks + tg];
            unsigned a1 = As[wm * 16 + g + 8][ks + tg];
            unsigned a2 = As[wm * 16 + g][ks + tg + 4];
            unsigned a3 = As[wm * 16 + g + 8][ks + tg + 4];
#pragma unroll
            for (int nt = 0; nt < 4; nt++) {
                unsigned b0 = Bs[ks + tg][wn * 32 + nt * 8 + g];
                unsigned b1 = Bs[ks + tg + 4][wn * 32 + nt * 8 + g];
                mma8(acc[nt], a0, a1, a2, a3, b0, b1);
            }
        }
        __syncthreads();
    }

    // stash z tile to smem so each (b,j) thread can gather its 4 gates
    int rl = wm * 16 + g;
#pragma unroll
    for (int nt = 0; nt < 4; nt++) {
        int cl = wn * 32 + nt * 8 + tg * 2;
        zs[rl][cl]         = acc[nt][0];
        zs[rl][cl + 1]     = acc[nt][1];
        zs[rl + 8][cl]     = acc[nt][2];
        zs[rl + 8][cl + 1] = acc[nt][3];
    }
    __syncthreads();

    for (int p = tid; p < 64 * 16; p += 256) {
        int r = p >> 4, j = p & 15;
        int b  = m0 + r;
        int jj = j0 + j;
        size_t xrow = ((size_t)b * T_ + t) * G4_;
        float zi = zs[r][j]      + xz[xrow + jj];
        float zf = zs[r][16 + j] + xz[xrow + 512 + jj];
        float zg = zs[r][32 + j] + xz[xrow + 1024 + jj];
        float zo = zs[r][48 + j] + xz[xrow + 1536 + jj];
        float iv = sigm(zi);
        float fv = sigm(zf);
        float gv = tanhf(zg);
        float ov = sigm(zo);
        int sidx = b * H_ + jj;
        float cv = fv * cst[sidx] + iv * gv;
        float hv = ov * tanhf(cv);
        cst[sidx]  = cv;
        hout[sidx] = hv;
        hs[((size_t)b * T_ + t) * H_ + jj] = hv;
    }
}

// ---------------- output heads: mu, softplus(sigma) ----------------
// one warp per (b,t) row; out layout: [mu (BT), sigma (BT)]
__global__ void k_heads(const float* __restrict__ hs,
                        const float* __restrict__ Wmu, const float* __restrict__ bmu,
                        const float* __restrict__ Wsig, const float* __restrict__ bsig,
                        float* __restrict__ out) {
    int wg  = (blockIdx.x * blockDim.x + threadIdx.x) >> 5;
    int lane = threadIdx.x & 31;
    if (wg >= BT_) return;
    const float* h = hs + (size_t)wg * H_;
    float smu = 0.0f, ssg = 0.0f;
#pragma unroll 4
    for (int k = lane; k < H_; k += 32) {
        float hv = h[k];
        smu += hv * Wmu[k];
        ssg += hv * Wsig[k];
    }
#pragma unroll
    for (int o = 16; o; o >>= 1) {
        smu += __shfl_xor_sync(0xffffffffu, smu, o);
        ssg += __shfl_xor_sync(0xffffffffu, ssg, o);
    }
    if (lane == 0) {
        out[wg] = smu + bmu[0];
        float x = ssg + bsig[0];
        out[BT_ + wg] = (x > 20.0f) ? x : log1pf(expf(x));
    }
}

// ---------------- launch ----------------
extern "C" void kernel_launch(void* const* d_in, const int* in_sizes, int n_in,
                              void* d_out, int out_size) {
    const float* x_cont = (const float*)d_in[0];
    const int*   cat0   = (const int*)  d_in[1];
    const int*   cat1   = (const int*)  d_in[2];
    const float* emb0   = (const float*)d_in[3];
    const float* emb1   = (const float*)d_in[4];
    const float* Wk1    = (const float*)d_in[5];
    const float* Wr1    = (const float*)d_in[6];
    const float* b1     = (const float*)d_in[7];
    const float* Wk2    = (const float*)d_in[8];
    const float* Wr2    = (const float*)d_in[9];
    const float* b2     = (const float*)d_in[10];
    const float* Wmu    = (const float*)d_in[11];
    const float* bmu    = (const float*)d_in[12];
    const float* Wsig   = (const float*)d_in[13];
    const float* bsig   = (const float*)d_in[14];
    float* out = (float*)d_out;

    float *px, *pxz, *phs, *ph0, *ph1, *pc;
    cudaGetSymbolAddress((void**)&px,  g_x);
    cudaGetSymbolAddress((void**)&pxz, g_xz);
    cudaGetSymbolAddress((void**)&phs, g_hs);
    cudaGetSymbolAddress((void**)&ph0, g_h0);
    cudaGetSymbolAddress((void**)&ph1, g_h1);
    cudaGetSymbolAddress((void**)&pc,  g_c);

    const int BH = B_ * H_;
    dim3 gemm_grid(BT_ / 64, G4_ / 64);   // (768, 32)
    dim3 step_grid(B_ / 64, H_ / 16);     // (4, 32)

    // ---- layer 1 ----
    k_zero<<<(BH + 255) / 256, 256>>>(ph0, pc, BH);
    k_build_x<<<(BT_ * DIN_ + 255) / 256, 256>>>(x_cont, cat0, cat1, emb0, emb1);
    k_gemm<<<gemm_grid, 256>>>(px, DIN_, DIN_, Wk1, b1, pxz);
    {
        const float* hin = ph0;
        float* hout = ph1;
        for (int t = 0; t < T_; t++) {
            k_step<<<step_grid, 256>>>(Wr1, pxz, t, hin, hout, pc, phs);
            const float* tmp = hout;
            hout = (float*)hin;
            hin  = tmp;
        }
    }

    // ---- layer 2 ----
    k_zero<<<(BH + 255) / 256, 256>>>(ph0, pc, BH);
    k_gemm<<<gemm_grid, 256>>>(phs, H_, H_, Wk2, b2, pxz);
    {
        const float* hin = ph0;
        float* hout = ph1;
        for (int t = 0; t < T_; t++) {
            k_step<<<step_grid, 256>>>(Wr2, pxz, t, hin, hout, pc, phs);
            const float* tmp = hout;
            hout = (float*)hin;
            hin  = tmp;
        }
    }

    // ---- heads ----
    k_heads<<<(BT_ * 32 + 255) / 256, 256>>>(phs, Wmu, bmu, Wsig, bsig, out);
}

// round 2
// speedup vs baseline: 3.9095x; 3.9095x over previous
#include <cuda_runtime.h>
#include <cuda_bf16.h>
#include <math.h>

// Problem constants
#define B_    256
#define T_    192
#define F_    8
#define E0_   32
#define E1_   16
#define DINP  64          // padded input dim (real 56)
#define H_    512
#define G4_   2048
#define BT_   (B_ * T_)   // 49152
#define KC    32

// ---------------- scratch (static device arrays; no allocation) ----------------
__device__ float g_x  [(size_t)BT_ * DINP];     // padded concat input
__device__ float g_wk1p[DINP * G4_];            // padded Wk1 (rows 56..63 zero)
__device__ float g_xz [(size_t)BT_ * G4_];      // precomputed input projection (+bias)
__device__ float g_hs [(size_t)BT_ * H_];       // per-step hidden outputs of current layer
__device__ float g_h0 [B_ * H_];                // ping-pong h state
__device__ float g_h1 [B_ * H_];
__device__ unsigned g_ctr[8];                   // group barriers (4 per layer)

// ---------------- helpers ----------------
__device__ __forceinline__ unsigned f2tf(float x) {
    unsigned r;
    asm("cvt.rna.tf32.f32 %0, %1;" : "=r"(r) : "f"(x));
    return r;
}

__device__ __forceinline__ void mma8(float* c,
                                     unsigned a0, unsigned a1, unsigned a2, unsigned a3,
                                     unsigned b0, unsigned b1) {
    asm volatile(
        "mma.sync.aligned.m16n8k8.row.col.f32.tf32.tf32.f32 "
        "{%0,%1,%2,%3},{%4,%5,%6,%7},{%8,%9},{%0,%1,%2,%3};\n"
        : "+f"(c[0]), "+f"(c[1]), "+f"(c[2]), "+f"(c[3])
        : "r"(a0), "r"(a1), "r"(a2), "r"(a3), "r"(b0), "r"(b1));
}

__device__ __forceinline__ float sigm(float x) { return 1.0f / (1.0f + expf(-x)); }

__device__ __forceinline__ void cpa16(void* dst, const void* src) {
    unsigned d = (unsigned)__cvta_generic_to_shared(dst);
    asm volatile("cp.async.ca.shared.global [%0], [%1], 16;\n" :: "r"(d), "l"(src));
}
#define CP_COMMIT asm volatile("cp.async.commit_group;\n")
#define CP_WAIT0  asm volatile("cp.async.wait_group 0;\n")
#define CP_WAIT1  asm volatile("cp.async.wait_group 1;\n")

// ---------------- tiny kernels ----------------
__global__ void k_init() {
    if (threadIdx.x < 8) g_ctr[threadIdx.x] = 0u;
}

__global__ void k_build_x(const float* __restrict__ xc,
                          const int* __restrict__ c0, const int* __restrict__ c1,
                          const float* __restrict__ e0, const float* __restrict__ e1) {
    int i = blockIdx.x * blockDim.x + threadIdx.x;
    if (i >= BT_ * DINP) return;
    int bt = i >> 6;
    int d  = i & 63;
    float v;
    if (d < F_)                 v = xc[bt * F_ + d];
    else if (d < F_ + E0_)      v = e0[c0[bt] * E0_ + (d - F_)];
    else if (d < F_ + E0_ + E1_) v = e1[c1[bt] * E1_ + (d - F_ - E0_)];
    else                        v = 0.0f;
    g_x[i] = v;
}

__global__ void k_padwk(const float* __restrict__ Wk1) {
    int i = blockIdx.x * blockDim.x + threadIdx.x;
    if (i >= DINP * G4_) return;
    int r = i >> 11, c = i & 2047;
    g_wk1p[i] = (r < 56) ? Wk1[r * G4_ + c] : 0.0f;
}

// ---------------- TF32 GEMM: C[M,2048] = A[M,K] @ W[K,2048] + bias ----------------
// CTA 64x64, 256 threads (8 warps, 4Mx2N), double-buffered cp.async, K % 32 == 0.
__global__ void __launch_bounds__(256)
k_gemm(const float* __restrict__ A, int lda, int K,
       const float* __restrict__ W, const float* __restrict__ bias,
       float* __restrict__ C) {
    __shared__ float As[2][64][36];
    __shared__ float Bs[2][32][72];
    int m0 = blockIdx.x * 64, n0 = blockIdx.y * 64;
    int tid = threadIdx.x;
    int lane = tid & 31, warp = tid >> 5;
    int wm = warp >> 1, wn = warp & 1;
    int g = lane >> 2, tg = lane & 3;

    float acc[4][4];
#pragma unroll
    for (int i = 0; i < 4; i++)
#pragma unroll
        for (int j = 0; j < 4; j++) acc[i][j] = 0.0f;

    int nch = K / KC;

    // prologue
    {
#pragma unroll
        for (int ii = 0; ii < 2; ii++) {
            int idx = tid + 256 * ii;
            int r = idx >> 3, q = idx & 7;
            cpa16(&As[0][r][q * 4], &A[(size_t)(m0 + r) * lda + q * 4]);
        }
#pragma unroll
        for (int ii = 0; ii < 2; ii++) {
            int idx = tid + 256 * ii;
            int k = idx >> 4, q = idx & 15;
            cpa16(&Bs[0][k][q * 4], &W[(size_t)k * G4_ + n0 + q * 4]);
        }
        CP_COMMIT;
    }

    for (int kc = 0; kc < nch; kc++) {
        int b = kc & 1;
        if (kc + 1 < nch) {
            int b2 = b ^ 1;
            int k0 = (kc + 1) * KC;
#pragma unroll
            for (int ii = 0; ii < 2; ii++) {
                int idx = tid + 256 * ii;
                int r = idx >> 3, q = idx & 7;
                cpa16(&As[b2][r][q * 4], &A[(size_t)(m0 + r) * lda + k0 + q * 4]);
            }
#pragma unroll
            for (int ii = 0; ii < 2; ii++) {
                int idx = tid + 256 * ii;
                int k = idx >> 4, q = idx & 15;
                cpa16(&Bs[b2][k][q * 4], &W[(size_t)(k0 + k) * G4_ + n0 + q * 4]);
            }
            CP_COMMIT;
            CP_WAIT1;
        } else {
            CP_WAIT0;
        }
        __syncthreads();
#pragma unroll
        for (int ks = 0; ks < KC; ks += 8) {
            unsigned a0 = f2tf(As[b][wm * 16 + g][ks + tg]);
            unsigned a1 = f2tf(As[b][wm * 16 + g + 8][ks + tg]);
            unsigned a2 = f2tf(As[b][wm * 16 + g][ks + tg + 4]);
            unsigned a3 = f2tf(As[b][wm * 16 + g + 8][ks + tg + 4]);
#pragma unroll
            for (int nt = 0; nt < 4; nt++) {
                unsigned b0 = f2tf(Bs[b][ks + tg][wn * 32 + nt * 8 + g]);
                unsigned b1 = f2tf(Bs[b][ks + tg + 4][wn * 32 + nt * 8 + g]);
                mma8(acc[nt], a0, a1, a2, a3, b0, b1);
            }
        }
        __syncthreads();
    }

    int rl = wm * 16 + g;
#pragma unroll
    for (int nt = 0; nt < 4; nt++) {
        int cl  = wn * 32 + nt * 8 + tg * 2;
        int col = n0 + cl;
        float bb0 = bias[col], bb1 = bias[col + 1];
        size_t o0 = (size_t)(m0 + rl) * G4_ + col;
        size_t o1 = (size_t)(m0 + rl + 8) * G4_ + col;
        C[o0]     = acc[nt][0] + bb0;
        C[o0 + 1] = acc[nt][1] + bb1;
        C[o1]     = acc[nt][2] + bb0;
        C[o1 + 1] = acc[nt][3] + bb1;
    }
}

// ---------------- persistent LSTM scan (one launch per layer) ----------------
// grid = (4, 32): CTA owns batch rows [m0, m0+64) and hidden cols [j0, j0+16)
// (gate z-columns j0+{0,512,1024,1536}). Wr slice resident in smem as tf32.
// Cell state in registers. Per-group (32 CTA) atomic barrier between steps.
__global__ void __launch_bounds__(256)
k_scan(const float* __restrict__ Wr, const float* __restrict__ xz,
       float* __restrict__ h0, float* __restrict__ h1,
       float* __restrict__ hs, unsigned* __restrict__ ctr) {
    extern __shared__ float sm[];
    unsigned* Bs = (unsigned*)sm;          // [512][72] tf32 Wr slice
    float* As = sm + 512 * 72;             // [2][64][36] h chunk double buffer
    float* zs = As + 2 * 64 * 36;          // [64][68] z tile
    float* xs = zs + 64 * 68;              // [64][68] xz gate tile (uses 64 cols)

    int m0 = blockIdx.x * 64;
    int j0 = blockIdx.y * 16;
    int gidx = blockIdx.x;
    int tid = threadIdx.x;
    int lane = tid & 31, warp = tid >> 5;
    int wm = warp >> 1, wn = warp & 1;
    int g = lane >> 2, tg = lane & 3;

    // preload Wr slice (once)
    for (int i = tid; i < 512 * 64; i += 256) {
        int k = i >> 6, c = i & 63;
        int col = ((c >> 4) << 9) + j0 + (c & 15);
        Bs[k * 72 + c] = f2tf(Wr[(size_t)k * G4_ + col]);
    }

    float creg[4] = {0.0f, 0.0f, 0.0f, 0.0f};
    __syncthreads();

    for (int t = 0; t < T_; t++) {
        const float* hin = (t & 1) ? h1 : h0;
        float* hout = (t & 1) ? h0 : h1;

        // prefetch this step's xz gate slices: 64 rows x 4 gates x 16 cols
        {
#pragma unroll
            for (int ii = 0; ii < 4; ii++) {
                int idx = tid + 256 * ii;       // 1024 quads
                int r = idx >> 4;               // batch row 0..63
                int gq = idx & 15;              // gate*4 + quad
                int gate = gq >> 2, q = gq & 3;
                cpa16(&xs[r * 68 + gate * 16 + q * 4],
                      &xz[((size_t)(m0 + r) * T_ + t) * G4_ + gate * 512 + j0 + q * 4]);
            }
            CP_COMMIT;
        }

        float acc[4][4];
#pragma unroll
        for (int i = 0; i < 4; i++)
#pragma unroll
            for (int j = 0; j < 4; j++) acc[i][j] = 0.0f;

        if (t > 0) {
            // prologue chunk 0
            {
#pragma unroll
                for (int ii = 0; ii < 2; ii++) {
                    int idx = tid + 256 * ii;
                    int r = idx >> 3, q = idx & 7;
                    cpa16(&As[(0 * 64 + r) * 36 + q * 4],
                          &hin[(m0 + r) * H_ + q * 4]);
                }
                CP_COMMIT;
            }
            for (int kc = 0; kc < 16; kc++) {
                int b = kc & 1;
                if (kc < 15) {
                    int b2 = b ^ 1;
                    int k0 = (kc + 1) * KC;
#pragma unroll
                    for (int ii = 0; ii < 2; ii++) {
                        int idx = tid + 256 * ii;
                        int r = idx >> 3, q = idx & 7;
                        cpa16(&As[(b2 * 64 + r) * 36 + q * 4],
                              &hin[(m0 + r) * H_ + k0 + q * 4]);
                    }
                    CP_COMMIT;
                    CP_WAIT1;
                } else {
                    CP_WAIT0;
                }
                __syncthreads();
                int kg = kc * KC;
#pragma unroll
                for (int ks = 0; ks < KC; ks += 8) {
                    unsigned a0 = f2tf(As[(b * 64 + wm * 16 + g) * 36 + ks + tg]);
                    unsigned a1 = f2tf(As[(b * 64 + wm * 16 + g + 8) * 36 + ks + tg]);
                    unsigned a2 = f2tf(As[(b * 64 + wm * 16 + g) * 36 + ks + tg + 4]);
                    unsigned a3 = f2tf(As[(b * 64 + wm * 16 + g + 8) * 36 + ks + tg + 4]);
#pragma unroll
                    for (int nt = 0; nt < 4; nt++) {
                        unsigned b0 = Bs[(size_t)(kg + ks + tg) * 72 + wn * 32 + nt * 8 + g];
                        unsigned b1 = Bs[(size_t)(kg + ks + tg + 4) * 72 + wn * 32 + nt * 8 + g];
                        mma8(acc[nt], a0, a1, a2, a3, b0, b1);
                    }
                }
                __syncthreads();
            }
        } else {
            CP_WAIT0;   // just the xz prefetch
        }

        // stash z tile
        int rl = wm * 16 + g;
#pragma unroll
        for (int nt = 0; nt < 4; nt++) {
            int cl = wn * 32 + nt * 8 + tg * 2;
            zs[rl * 68 + cl]           = acc[nt][0];
            zs[rl * 68 + cl + 1]       = acc[nt][1];
            zs[(rl + 8) * 68 + cl]     = acc[nt][2];
            zs[(rl + 8) * 68 + cl + 1] = acc[nt][3];
        }
        __syncthreads();

        // cell update (c in registers)
#pragma unroll
        for (int it = 0; it < 4; it++) {
            int p = tid + 256 * it;
            int r = p >> 4, j = p & 15;
            int b = m0 + r, jj = j0 + j;
            float zi = zs[r * 68 + j]      + xs[r * 68 + j];
            float zf = zs[r * 68 + 16 + j] + xs[r * 68 + 16 + j];
            float zg = zs[r * 68 + 32 + j] + xs[r * 68 + 32 + j];
            float zo = zs[r * 68 + 48 + j] + xs[r * 68 + 48 + j];
            float iv = sigm(zi);
            float fv = sigm(zf);
            float gv = tanhf(zg);
            float ov = sigm(zo);
            float cv = fv * creg[it] + iv * gv;
            float hv = ov * tanhf(cv);
            creg[it] = cv;
            hout[b * H_ + jj] = hv;
            hs[((size_t)b * T_ + t) * H_ + jj] = hv;
        }

        // group barrier (32 CTAs sharing m0)
        __threadfence();
        __syncthreads();
        if (tid == 0) {
            atomicAdd(&ctr[gidx], 1u);
            unsigned target = 32u * (unsigned)(t + 1);
            unsigned v;
            do {
                asm volatile("ld.acquire.gpu.u32 %0, [%1];" : "=r"(v) : "l"(ctr + gidx));
            } while (v < target);
        }
        __syncthreads();
    }
}

// ---------------- output heads: mu, softplus(sigma) ----------------
__global__ void k_heads(const float* __restrict__ hs,
                        const float* __restrict__ Wmu, const float* __restrict__ bmu,
                        const float* __restrict__ Wsig, const float* __restrict__ bsig,
                        float* __restrict__ out) {
    int wg  = (blockIdx.x * blockDim.x + threadIdx.x) >> 5;
    int lane = threadIdx.x & 31;
    if (wg >= BT_) return;
    const float* h = hs + (size_t)wg * H_;
    float smu = 0.0f, ssg = 0.0f;
#pragma unroll 4
    for (int k = lane; k < H_; k += 32) {
        float hv = h[k];
        smu += hv * Wmu[k];
        ssg += hv * Wsig[k];
    }
#pragma unroll
    for (int o = 16; o; o >>= 1) {
        smu += __shfl_xor_sync(0xffffffffu, smu, o);
        ssg += __shfl_xor_sync(0xffffffffu, ssg, o);
    }
    if (lane == 0) {
        out[wg] = smu + bmu[0];
        float x = ssg + bsig[0];
        out[BT_ + wg] = (x > 20.0f) ? x : log1pf(expf(x));
    }
}

// ---------------- launch ----------------
extern "C" void kernel_launch(void* const* d_in, const int* in_sizes, int n_in,
                              void* d_out, int out_size) {
    const float* x_cont = (const float*)d_in[0];
    const int*   cat0   = (const int*)  d_in[1];
    const int*   cat1   = (const int*)  d_in[2];
    const float* emb0   = (const float*)d_in[3];
    const float* emb1   = (const float*)d_in[4];
    const float* Wk1    = (const float*)d_in[5];
    const float* Wr1    = (const float*)d_in[6];
    const float* b1     = (const float*)d_in[7];
    const float* Wk2    = (const float*)d_in[8];
    const float* Wr2    = (const float*)d_in[9];
    const float* b2     = (const float*)d_in[10];
    const float* Wmu    = (const float*)d_in[11];
    const float* bmu    = (const float*)d_in[12];
    const float* Wsig   = (const float*)d_in[13];
    const float* bsig   = (const float*)d_in[14];
    float* out = (float*)d_out;

    float *px, *pwk, *pxz, *phs, *ph0, *ph1;
    unsigned* pctr;
    cudaGetSymbolAddress((void**)&px,  g_x);
    cudaGetSymbolAddress((void**)&pwk, g_wk1p);
    cudaGetSymbolAddress((void**)&pxz, g_xz);
    cudaGetSymbolAddress((void**)&phs, g_hs);
    cudaGetSymbolAddress((void**)&ph0, g_h0);
    cudaGetSymbolAddress((void**)&ph1, g_h1);
    cudaGetSymbolAddress((void**)&pctr, g_ctr);

    const int SMEM_SCAN = (512 * 72 + 2 * 64 * 36 + 64 * 68 + 64 * 68) * 4;
    cudaFuncSetAttribute(k_scan, cudaFuncAttributeMaxDynamicSharedMemorySize, SMEM_SCAN);

    dim3 gemm_grid(BT_ / 64, G4_ / 64);   // (768, 32)
    dim3 scan_grid(B_ / 64, H_ / 16);     // (4, 32)

    k_init<<<1, 32>>>();
    k_build_x<<<(BT_ * DINP + 255) / 256, 256>>>(x_cont, cat0, cat1, emb0, emb1);
    k_padwk<<<(DINP * G4_ + 255) / 256, 256>>>(Wk1);

    // ---- layer 1 ----
    k_gemm<<<gemm_grid, 256>>>(px, DINP, DINP, pwk, b1, pxz);
    k_scan<<<scan_grid, 256, SMEM_SCAN>>>(Wr1, pxz, ph0, ph1, phs, pctr);

    // ---- layer 2 ----
    k_gemm<<<gemm_grid, 256>>>(phs, H_, H_, Wk2, b2, pxz);
    k_scan<<<scan_grid, 256, SMEM_SCAN>>>(Wr2, pxz, ph0, ph1, phs, pctr + 4);

    // ---- heads ----
    k_heads<<<(BT_ * 32 + 255) / 256, 256>>>(phs, Wmu, bmu, Wsig, bsig, out);
}

// round 4
// speedup vs baseline: 6.3915x; 1.6349x over previous
#include <cuda_runtime.h>
#include <cuda_bf16.h>
#include <math.h>
#include <stdint.h>

// Problem constants
#define B_    256
#define T_    192
#define F_    8
#define E0_   32
#define E1_   16
#define DINP  64          // padded input dim (real 56)
#define H_    512
#define G4_   2048
#define BT_   (B_ * T_)   // 49152
#define KC    32

// Scan smem layout (bytes)
#define NBH   520                         // Bs row length in halves (512 + 8 pad)
#define NAH   72                          // As row length in halves (64 + 8 pad)
#define SC_BS_BYTES (64 * NBH * 2)        // 66560
#define SC_AS_BYTES (3 * 64 * NAH * 2)    // 27648
#define SC_ZS_BYTES (64 * 68 * 4)         // 17408
#define SC_XS_BYTES (64 * 68 * 4)         // 17408
#define SC_SMEM (SC_BS_BYTES + SC_AS_BYTES + SC_ZS_BYTES + SC_XS_BYTES)

// ---------------- scratch (static device arrays; no allocation) ----------------
__device__ float g_x  [(size_t)BT_ * DINP];       // padded concat input (fp32)
__device__ float g_wk1p[DINP * G4_];              // padded Wk1
__device__ float g_xz [(size_t)BT_ * G4_];        // input projection (+bias), fp32
__device__ __nv_bfloat16 g_hs1[(size_t)BT_ * H_]; // layer1 hidden outputs (bf16)
__device__ __nv_bfloat16 g_hs2[(size_t)BT_ * H_]; // layer2 hidden outputs (bf16)
__device__ unsigned g_ctr[8];

// ---------------- helpers ----------------
__device__ __forceinline__ unsigned f2tf(float x) {
    unsigned r;
    asm("cvt.rna.tf32.f32 %0, %1;" : "=r"(r) : "f"(x));
    return r;
}

__device__ __forceinline__ void mma8(float* c,
                                     unsigned a0, unsigned a1, unsigned a2, unsigned a3,
                                     unsigned b0, unsigned b1) {
    asm volatile(
        "mma.sync.aligned.m16n8k8.row.col.f32.tf32.tf32.f32 "
        "{%0,%1,%2,%3},{%4,%5,%6,%7},{%8,%9},{%0,%1,%2,%3};\n"
        : "+f"(c[0]), "+f"(c[1]), "+f"(c[2]), "+f"(c[3])
        : "r"(a0), "r"(a1), "r"(a2), "r"(a3), "r"(b0), "r"(b1));
}

__device__ __forceinline__ void mma16bf(float* c,
                                        unsigned a0, unsigned a1, unsigned a2, unsigned a3,
                                        unsigned b0, unsigned b1) {
    asm volatile(
        "mma.sync.aligned.m16n8k16.row.col.f32.bf16.bf16.f32 "
        "{%0,%1,%2,%3},{%4,%5,%6,%7},{%8,%9},{%0,%1,%2,%3};\n"
        : "+f"(c[0]), "+f"(c[1]), "+f"(c[2]), "+f"(c[3])
        : "r"(a0), "r"(a1), "r"(a2), "r"(a3), "r"(b0), "r"(b1));
}

__device__ __forceinline__ void ldsm4(unsigned& r0, unsigned& r1, unsigned& r2, unsigned& r3,
                                      const void* p) {
    unsigned a = (unsigned)__cvta_generic_to_shared(p);
    asm volatile("ldmatrix.sync.aligned.m8n8.x4.shared.b16 {%0,%1,%2,%3}, [%4];"
                 : "=r"(r0), "=r"(r1), "=r"(r2), "=r"(r3) : "r"(a));
}

__device__ __forceinline__ float sigm(float x) { return 1.0f / (1.0f + expf(-x)); }

__device__ __forceinline__ void cpa16(void* dst, const void* src) {
    unsigned d = (unsigned)__cvta_generic_to_shared(dst);
    asm volatile("cp.async.ca.shared.global [%0], [%1], 16;\n" :: "r"(d), "l"(src));
}
#define CP_COMMIT asm volatile("cp.async.commit_group;\n")
#define CP_WAIT0  asm volatile("cp.async.wait_group 0;\n")
#define CP_WAIT1  asm volatile("cp.async.wait_group 1;\n")

// ---------------- tiny kernels ----------------
__global__ void k_init() {
    if (threadIdx.x < 8) g_ctr[threadIdx.x] = 0u;
}

__global__ void k_build_x(const float* __restrict__ xc,
                          const int* __restrict__ c0, const int* __restrict__ c1,
                          const float* __restrict__ e0, const float* __restrict__ e1) {
    int i = blockIdx.x * blockDim.x + threadIdx.x;
    if (i >= BT_ * DINP) return;
    int bt = i >> 6;
    int d  = i & 63;
    float v;
    if (d < F_)                  v = xc[bt * F_ + d];
    else if (d < F_ + E0_)       v = e0[c0[bt] * E0_ + (d - F_)];
    else if (d < F_ + E0_ + E1_) v = e1[c1[bt] * E1_ + (d - F_ - E0_)];
    else                         v = 0.0f;
    g_x[i] = v;
}

__global__ void k_padwk(const float* __restrict__ Wk1) {
    int i = blockIdx.x * blockDim.x + threadIdx.x;
    if (i >= DINP * G4_) return;
    int r = i >> 11, c = i & 2047;
    g_wk1p[i] = (r < 56) ? Wk1[r * G4_ + c] : 0.0f;
}

// ---------------- TF32 GEMM (fp32 A): C[M,2048] = A[M,K] @ W[K,2048] + bias ----------------
__global__ void __launch_bounds__(256)
k_gemm(const float* __restrict__ A, int lda, int K,
       const float* __restrict__ W, const float* __restrict__ bias,
       float* __restrict__ C) {
    __shared__ float As[2][64][36];
    __shared__ float Bs[2][32][72];
    int m0 = blockIdx.x * 64, n0 = blockIdx.y * 64;
    int tid = threadIdx.x;
    int lane = tid & 31, warp = tid >> 5;
    int wm = warp >> 1, wn = warp & 1;
    int g = lane >> 2, tg = lane & 3;

    float acc[4][4];
#pragma unroll
    for (int i = 0; i < 4; i++)
#pragma unroll
        for (int j = 0; j < 4; j++) acc[i][j] = 0.0f;

    int nch = K / KC;
    {
#pragma unroll
        for (int ii = 0; ii < 2; ii++) {
            int idx = tid + 256 * ii;
            int r = idx >> 3, q = idx & 7;
            cpa16(&As[0][r][q * 4], &A[(size_t)(m0 + r) * lda + q * 4]);
        }
#pragma unroll
        for (int ii = 0; ii < 2; ii++) {
            int idx = tid + 256 * ii;
            int k = idx >> 4, q = idx & 15;
            cpa16(&Bs[0][k][q * 4], &W[(size_t)k * G4_ + n0 + q * 4]);
        }
        CP_COMMIT;
    }

    for (int kc = 0; kc < nch; kc++) {
        int b = kc & 1;
        if (kc + 1 < nch) {
            int b2 = b ^ 1;
            int k0 = (kc + 1) * KC;
#pragma unroll
            for (int ii = 0; ii < 2; ii++) {
                int idx = tid + 256 * ii;
                int r = idx >> 3, q = idx & 7;
                cpa16(&As[b2][r][q * 4], &A[(size_t)(m0 + r) * lda + k0 + q * 4]);
            }
#pragma unroll
            for (int ii = 0; ii < 2; ii++) {
                int idx = tid + 256 * ii;
                int k = idx >> 4, q = idx & 15;
                cpa16(&Bs[b2][k][q * 4], &W[(size_t)(k0 + k) * G4_ + n0 + q * 4]);
            }
            CP_COMMIT;
            CP_WAIT1;
        } else {
            CP_WAIT0;
        }
        __syncthreads();
#pragma unroll
        for (int ks = 0; ks < KC; ks += 8) {
            unsigned a0 = f2tf(As[b][wm * 16 + g][ks + tg]);
            unsigned a1 = f2tf(As[b][wm * 16 + g + 8][ks + tg]);
            unsigned a2 = f2tf(As[b][wm * 16 + g][ks + tg + 4]);
            unsigned a3 = f2tf(As[b][wm * 16 + g + 8][ks + tg + 4]);
#pragma unroll
            for (int nt = 0; nt < 4; nt++) {
                unsigned b0 = f2tf(Bs[b][ks + tg][wn * 32 + nt * 8 + g]);
                unsigned b1 = f2tf(Bs[b][ks + tg + 4][wn * 32 + nt * 8 + g]);
                mma8(acc[nt], a0, a1, a2, a3, b0, b1);
            }
        }
        __syncthreads();
    }

    int rl = wm * 16 + g;
#pragma unroll
    for (int nt = 0; nt < 4; nt++) {
        int cl  = wn * 32 + nt * 8 + tg * 2;
        int col = n0 + cl;
        float bb0 = bias[col], bb1 = bias[col + 1];
        size_t o0 = (size_t)(m0 + rl) * G4_ + col;
        size_t o1 = (size_t)(m0 + rl + 8) * G4_ + col;
        C[o0]     = acc[nt][0] + bb0;
        C[o0 + 1] = acc[nt][1] + bb1;
        C[o1]     = acc[nt][2] + bb0;
        C[o1 + 1] = acc[nt][3] + bb1;
    }
}

// ---------------- TF32 GEMM with bf16 A (layer-2 input projection), K=512 ----------------
__global__ void __launch_bounds__(256)
k_gemm_b(const __nv_bfloat16* __restrict__ A,
         const float* __restrict__ W, const float* __restrict__ bias,
         float* __restrict__ C) {
    __shared__ __nv_bfloat16 As[2][64][40];
    __shared__ float Bs[2][32][72];
    int m0 = blockIdx.x * 64, n0 = blockIdx.y * 64;
    int tid = threadIdx.x;
    int lane = tid & 31, warp = tid >> 5;
    int wm = warp >> 1, wn = warp & 1;
    int g = lane >> 2, tg = lane & 3;

    float acc[4][4];
#pragma unroll
    for (int i = 0; i < 4; i++)
#pragma unroll
        for (int j = 0; j < 4; j++) acc[i][j] = 0.0f;

    {
        int r = tid >> 2, q = tid & 3;
        cpa16(&As[0][r][q * 8], &A[(size_t)(m0 + r) * H_ + q * 8]);
#pragma unroll
        for (int ii = 0; ii < 2; ii++) {
            int idx = tid + 256 * ii;
            int k = idx >> 4, qq = idx & 15;
            cpa16(&Bs[0][k][qq * 4], &W[(size_t)k * G4_ + n0 + qq * 4]);
        }
        CP_COMMIT;
    }

    for (int kc = 0; kc < 16; kc++) {
        int b = kc & 1;
        if (kc < 15) {
            int b2 = b ^ 1;
            int k0 = (kc + 1) * KC;
            int r = tid >> 2, q = tid & 3;
            cpa16(&As[b2][r][q * 8], &A[(size_t)(m0 + r) * H_ + k0 + q * 8]);
#pragma unroll
            for (int ii = 0; ii < 2; ii++) {
                int idx = tid + 256 * ii;
                int k = idx >> 4, qq = idx & 15;
                cpa16(&Bs[b2][k][qq * 4], &W[(size_t)(k0 + k) * G4_ + n0 + qq * 4]);
            }
            CP_COMMIT;
            CP_WAIT1;
        } else {
            CP_WAIT0;
        }
        __syncthreads();
#pragma unroll
        for (int ks = 0; ks < KC; ks += 8) {
            unsigned a0 = __float_as_uint(__bfloat162float(As[b][wm * 16 + g][ks + tg]));
            unsigned a1 = __float_as_uint(__bfloat162float(As[b][wm * 16 + g + 8][ks + tg]));
            unsigned a2 = __float_as_uint(__bfloat162float(As[b][wm * 16 + g][ks + tg + 4]));
            unsigned a3 = __float_as_uint(__bfloat162float(As[b][wm * 16 + g + 8][ks + tg + 4]));
#pragma unroll
            for (int nt = 0; nt < 4; nt++) {
                unsigned b0 = f2tf(Bs[b][ks + tg][wn * 32 + nt * 8 + g]);
                unsigned b1 = f2tf(Bs[b][ks + tg + 4][wn * 32 + nt * 8 + g]);
                mma8(acc[nt], a0, a1, a2, a3, b0, b1);
            }
        }
        __syncthreads();
    }

    int rl = wm * 16 + g;
#pragma unroll
    for (int nt = 0; nt < 4; nt++) {
        int cl  = wn * 32 + nt * 8 + tg * 2;
        int col = n0 + cl;
        float bb0 = bias[col], bb1 = bias[col + 1];
        size_t o0 = (size_t)(m0 + rl) * G4_ + col;
        size_t o1 = (size_t)(m0 + rl + 8) * G4_ + col;
        C[o0]     = acc[nt][0] + bb0;
        C[o0 + 1] = acc[nt][1] + bb1;
        C[o1]     = acc[nt][2] + bb0;
        C[o1 + 1] = acc[nt][3] + bb1;
    }
}

// ---------------- persistent bf16 LSTM scan (ldmatrix + mma m16n8k16) ----------------
// grid (4, 32), 256 threads. CTA: 64 batch rows x 64 z-cols (16 hidden j x 4 gates).
// Wr slice resident in smem bf16 [64n][520k]. Per step: triple-buffered cp.async
// staging of h[t-1] bf16 in 8 K-chunks of 64, ldmatrix fragments, 128 HMMA/warp,
// fused cell update (c in regs, fp32), h written bf16 to hs.
__global__ void __launch_bounds__(256)
k_scan(const float* __restrict__ Wr, const float* __restrict__ xz,
       __nv_bfloat16* __restrict__ hs, unsigned* __restrict__ ctr) {
    extern __shared__ char smem[];
    __nv_bfloat16* Bs = reinterpret_cast<__nv_bfloat16*>(smem);
    __nv_bfloat16* Asm = reinterpret_cast<__nv_bfloat16*>(smem + SC_BS_BYTES);
    float* zs = reinterpret_cast<float*>(smem + SC_BS_BYTES + SC_AS_BYTES);
    float* xs = zs + 64 * 68;

    int m0 = blockIdx.x * 64;
    int j0 = blockIdx.y * 16;
    int gidx = blockIdx.x;
    int tid = threadIdx.x;
    int lane = tid & 31, warp = tid >> 5;
    int wm = warp >> 1, wn = warp & 1;
    int g = lane >> 2, tg = lane & 3;

    // preload Wr slice -> Bs[n][k] bf16 (n = gate*16-col group order, k 0..511)
    for (int i = tid; i < 64 * 512; i += 256) {
        int c = i & 63, k = i >> 6;
        int col = ((c >> 4) << 9) + j0 + (c & 15);
        Bs[c * NBH + k] = __float2bfloat16(Wr[(size_t)k * G4_ + col]);
    }
    __syncthreads();

    // ldmatrix address precompute
    int a_row = wm * 16 + (lane & 7) + ((lane >> 3) & 1) * 8;
    int a_koff = ((lane >> 4) & 1) * 8;
    int b_nl[2], b_koff;
    b_koff = ((lane >> 3) & 1) * 8;
#pragma unroll
    for (int np = 0; np < 2; np++)
        b_nl[np] = wn * 32 + np * 16 + ((lane >> 4) & 1) * 8 + (lane & 7);

    float creg[4] = {0.0f, 0.0f, 0.0f, 0.0f};

    for (int t = 0; t < T_; t++) {
        // prefetch this step's xz gate slices: 64 rows x 4 gates x 16 cols (fp32)
#pragma unroll
        for (int ii = 0; ii < 4; ii++) {
            int idx = tid + 256 * ii;
            int r = idx >> 4;
            int gq = idx & 15;
            int gate = gq >> 2, q = gq & 3;
            cpa16(&xs[r * 68 + gate * 16 + q * 4],
                  &xz[((size_t)(m0 + r) * T_ + t) * G4_ + gate * 512 + j0 + q * 4]);
        }
        CP_COMMIT;

        float acc[4][4];
#pragma unroll
        for (int i = 0; i < 4; i++)
#pragma unroll
            for (int j = 0; j < 4; j++) acc[i][j] = 0.0f;

        if (t > 0) {
            const __nv_bfloat16* hsrc = hs;
            // stage chunk 0
#pragma unroll
            for (int ii = 0; ii < 2; ii++) {
                int idx = tid + 256 * ii;
                int r = idx >> 3, q = idx & 7;
                cpa16(&Asm[(0 * 64 + r) * NAH + q * 8],
                      &hsrc[((size_t)(m0 + r) * T_ + (t - 1)) * H_ + q * 8]);
            }
            CP_COMMIT;

            for (int kc = 0; kc < 8; kc++) {
                if (kc < 7) {
                    int bufn = (kc + 1) % 3;
                    int k0 = (kc + 1) * 64;
#pragma unroll
                    for (int ii = 0; ii < 2; ii++) {
                        int idx = tid + 256 * ii;
                        int r = idx >> 3, q = idx & 7;
                        cpa16(&Asm[(bufn * 64 + r) * NAH + q * 8],
                              &hsrc[((size_t)(m0 + r) * T_ + (t - 1)) * H_ + k0 + q * 8]);
                    }
                    CP_COMMIT;
                    CP_WAIT1;
                } else {
                    CP_WAIT0;
                }
                __syncthreads();

                const __nv_bfloat16* Ab = Asm + (kc % 3) * 64 * NAH;
                int kbase = kc * 64;
#pragma unroll
                for (int ks = 0; ks < 4; ks++) {
                    unsigned a0, a1, a2, a3;
                    ldsm4(a0, a1, a2, a3, &Ab[a_row * NAH + ks * 16 + a_koff]);
#pragma unroll
                    for (int np = 0; np < 2; np++) {
                        unsigned c0, c1, c2, c3;
                        ldsm4(c0, c1, c2, c3,
                              &Bs[b_nl[np] * NBH + kbase + ks * 16 + b_koff]);
                        mma16bf(acc[np * 2],     a0, a1, a2, a3, c0, c1);
                        mma16bf(acc[np * 2 + 1], a0, a1, a2, a3, c2, c3);
                    }
                }
            }
        } else {
            CP_WAIT0;
        }

        // stash z tile
        int rl = wm * 16 + g;
#pragma unroll
        for (int nt = 0; nt < 4; nt++) {
            int cl = wn * 32 + nt * 8 + tg * 2;
            zs[rl * 68 + cl]           = acc[nt][0];
            zs[rl * 68 + cl + 1]       = acc[nt][1];
            zs[(rl + 8) * 68 + cl]     = acc[nt][2];
            zs[(rl + 8) * 68 + cl + 1] = acc[nt][3];
        }
        __syncthreads();

        // fused cell update (c-state register-resident)
#pragma unroll
        for (int it = 0; it < 4; it++) {
            int p = tid + 256 * it;
            int r = p >> 4, j = p & 15;
            int b = m0 + r, jj = j0 + j;
            float zi = zs[r * 68 + j]      + xs[r * 68 + j];
            float zf = zs[r * 68 + 16 + j] + xs[r * 68 + 16 + j];
            float zg = zs[r * 68 + 32 + j] + xs[r * 68 + 32 + j];
            float zo = zs[r * 68 + 48 + j] + xs[r * 68 + 48 + j];
            float iv = sigm(zi);
            float fv = sigm(zf);
            float gv = tanhf(zg);
            float ov = sigm(zo);
            float cv = fv * creg[it] + iv * gv;
            float hv = ov * tanhf(cv);
            creg[it] = cv;
            hs[((size_t)b * T_ + t) * H_ + jj] = __float2bfloat16(hv);
        }

        // inter-CTA group barrier (32 CTAs share this batch group)
        __threadfence();
        __syncthreads();
        if (tid == 0) {
            atomicAdd(ctr + gidx, 1u);
            unsigned tgt = 32u * (unsigned)(t + 1);
            unsigned v;
            do {
                asm volatile("ld.acquire.gpu.u32 %0, [%1];" : "=r"(v) : "l"(ctr + gidx));
                if (v < tgt) __nanosleep(32);
            } while (v < tgt);
        }
        __syncthreads();
    }
}

// ---------------- output heads: mu, softplus(sigma) (bf16 hs) ----------------
__global__ void k_heads(const __nv_bfloat16* __restrict__ hs,
                        const float* __restrict__ Wmu, const float* __restrict__ bmu,
                        const float* __restrict__ Wsig, const float* __restrict__ bsig,
                        float* __restrict__ out) {
    int wg  = (blockIdx.x * blockDim.x + threadIdx.x) >> 5;
    int lane = threadIdx.x & 31;
    if (wg >= BT_) return;
    const __nv_bfloat16* h = hs + (size_t)wg * H_;
    float smu = 0.0f, ssg = 0.0f;
#pragma unroll 4
    for (int k = lane * 2; k < H_; k += 64) {
        __nv_bfloat162 hh = *reinterpret_cast<const __nv_bfloat162*>(h + k);
        float h0 = __bfloat162float(hh.x), h1 = __bfloat162float(hh.y);
        smu += h0 * Wmu[k] + h1 * Wmu[k + 1];
        ssg += h0 * Wsig[k] + h1 * Wsig[k + 1];
    }
#pragma unroll
    for (int o = 16; o; o >>= 1) {
        smu += __shfl_xor_sync(0xffffffffu, smu, o);
        ssg += __shfl_xor_sync(0xffffffffu, ssg, o);
    }
    if (lane == 0) {
        out[wg] = smu + bmu[0];
        float x = ssg + bsig[0];
        out[BT_ + wg] = (x > 20.0f) ? x : log1pf(expf(x));
    }
}

// ---------------- launch ----------------
extern "C" void kernel_launch(void* const* d_in, const int* in_sizes, int n_in,
                              void* d_out, int out_size) {
    const float* x_cont = (const float*)d_in[0];
    const int*   cat0   = (const int*)  d_in[1];
    const int*   cat1   = (const int*)  d_in[2];
    const float* emb0   = (const float*)d_in[3];
    const float* emb1   = (const float*)d_in[4];
    const float* Wk1    = (const float*)d_in[5];
    const float* Wr1    = (const float*)d_in[6];
    const float* b1     = (const float*)d_in[7];
    const float* Wk2    = (const float*)d_in[8];
    const float* Wr2    = (const float*)d_in[9];
    const float* b2     = (const float*)d_in[10];
    const float* Wmu    = (const float*)d_in[11];
    const float* bmu    = (const float*)d_in[12];
    const float* Wsig   = (const float*)d_in[13];
    const float* bsig   = (const float*)d_in[14];
    float* out = (float*)d_out;

    float *px, *pwk, *pxz;
    __nv_bfloat16 *ph1, *ph2;
    unsigned* pctr;
    cudaGetSymbolAddress((void**)&px,  g_x);
    cudaGetSymbolAddress((void**)&pwk, g_wk1p);
    cudaGetSymbolAddress((void**)&pxz, g_xz);
    cudaGetSymbolAddress((void**)&ph1, g_hs1);
    cudaGetSymbolAddress((void**)&ph2, g_hs2);
    cudaGetSymbolAddress((void**)&pctr, g_ctr);

    cudaFuncSetAttribute(k_scan, cudaFuncAttributeMaxDynamicSharedMemorySize, SC_SMEM);

    dim3 gemm_grid(BT_ / 64, G4_ / 64);   // (768, 32)
    dim3 scan_grid(4, 32);                // 128 persistent CTAs

    k_init<<<1, 32>>>();
    k_build_x<<<(BT_ * DINP + 255) / 256, 256>>>(x_cont, cat0, cat1, emb0, emb1);
    k_padwk<<<(DINP * G4_ + 255) / 256, 256>>>(Wk1);

    // ---- layer 1 ----
    k_gemm<<<gemm_grid, 256>>>(px, DINP, DINP, pwk, b1, pxz);
    k_scan<<<scan_grid, 256, SC_SMEM>>>(Wr1, pxz, ph1, pctr);

    // ---- layer 2 ----
    k_gemm_b<<<gemm_grid, 256>>>(ph1, Wk2, b2, pxz);
    k_scan<<<scan_grid, 256, SC_SMEM>>>(Wr2, pxz, ph2, pctr + 4);

    // ---- heads ----
    k_heads<<<(BT_ * 32 + 255) / 256, 256>>>(ph2, Wmu, bmu, Wsig, bsig, out);
}

// round 5
// speedup vs baseline: 7.0574x; 1.1042x over previous
#include <cuda_runtime.h>
#include <cuda_bf16.h>
#include <math.h>
#include <stdint.h>

// Problem constants
#define B_    256
#define T_    192
#define F_    8
#define E0_   32
#define E1_   16
#define DINP  64          // padded input dim (real 56)
#define H_    512
#define G4_   2048
#define BT_   (B_ * T_)   // 49152
#define KC    32

// Scan smem: Bs [64][520] bf16 + As [64][520] bf16
#define NROW  520
#define SC_TILE_BYTES (64 * NROW * 2)
#define SC_SMEM (2 * SC_TILE_BYTES)

// ---------------- scratch (static device arrays; no allocation) ----------------
__device__ float g_x  [(size_t)BT_ * DINP];            // padded concat input (fp32)
__device__ float g_wk1p[DINP * G4_];                   // padded Wk1
__device__ __nv_bfloat16 g_xz [(size_t)BT_ * G4_];     // input projection (+bias), bf16
__device__ __nv_bfloat16 g_hs1[(size_t)BT_ * H_];      // layer1 hidden outputs (bf16)
__device__ __nv_bfloat16 g_hs2[(size_t)BT_ * H_];      // layer2 hidden outputs (bf16)
__device__ unsigned g_ctr[8];

// ---------------- helpers ----------------
__device__ __forceinline__ unsigned f2tf(float x) {
    unsigned r;
    asm("cvt.rna.tf32.f32 %0, %1;" : "=r"(r) : "f"(x));
    return r;
}

__device__ __forceinline__ void mma8(float* c,
                                     unsigned a0, unsigned a1, unsigned a2, unsigned a3,
                                     unsigned b0, unsigned b1) {
    asm volatile(
        "mma.sync.aligned.m16n8k8.row.col.f32.tf32.tf32.f32 "
        "{%0,%1,%2,%3},{%4,%5,%6,%7},{%8,%9},{%0,%1,%2,%3};\n"
        : "+f"(c[0]), "+f"(c[1]), "+f"(c[2]), "+f"(c[3])
        : "r"(a0), "r"(a1), "r"(a2), "r"(a3), "r"(b0), "r"(b1));
}

__device__ __forceinline__ void mma16bf(float* c,
                                        unsigned a0, unsigned a1, unsigned a2, unsigned a3,
                                        unsigned b0, unsigned b1) {
    asm volatile(
        "mma.sync.aligned.m16n8k16.row.col.f32.bf16.bf16.f32 "
        "{%0,%1,%2,%3},{%4,%5,%6,%7},{%8,%9},{%0,%1,%2,%3};\n"
        : "+f"(c[0]), "+f"(c[1]), "+f"(c[2]), "+f"(c[3])
        : "r"(a0), "r"(a1), "r"(a2), "r"(a3), "r"(b0), "r"(b1));
}

__device__ __forceinline__ void ldsm4(unsigned& r0, unsigned& r1, unsigned& r2, unsigned& r3,
                                      const void* p) {
    unsigned a = (unsigned)__cvta_generic_to_shared(p);
    asm volatile("ldmatrix.sync.aligned.m8n8.x4.shared.b16 {%0,%1,%2,%3}, [%4];"
                 : "=r"(r0), "=r"(r1), "=r"(r2), "=r"(r3) : "r"(a));
}

__device__ __forceinline__ float sigm(float x) { return 1.0f / (1.0f + expf(-x)); }

__device__ __forceinline__ void cpa16(void* dst, const void* src) {
    unsigned d = (unsigned)__cvta_generic_to_shared(dst);
    asm volatile("cp.async.ca.shared.global [%0], [%1], 16;\n" :: "r"(d), "l"(src));
}
#define CP_COMMIT asm volatile("cp.async.commit_group;\n")
#define CP_WAIT0  asm volatile("cp.async.wait_group 0;\n")
#define CP_WAIT1  asm volatile("cp.async.wait_group 1;\n")

// ---------------- tiny kernels ----------------
__global__ void k_init() {
    if (threadIdx.x < 8) g_ctr[threadIdx.x] = 0u;
}

__global__ void k_build_x(const float* __restrict__ xc,
                          const int* __restrict__ c0, const int* __restrict__ c1,
                          const float* __restrict__ e0, const float* __restrict__ e1) {
    int i = blockIdx.x * blockDim.x + threadIdx.x;
    if (i >= BT_ * DINP) return;
    int bt = i >> 6;
    int d  = i & 63;
    float v;
    if (d < F_)                  v = xc[bt * F_ + d];
    else if (d < F_ + E0_)       v = e0[c0[bt] * E0_ + (d - F_)];
    else if (d < F_ + E0_ + E1_) v = e1[c1[bt] * E1_ + (d - F_ - E0_)];
    else                         v = 0.0f;
    g_x[i] = v;
}

__global__ void k_padwk(const float* __restrict__ Wk1) {
    int i = blockIdx.x * blockDim.x + threadIdx.x;
    if (i >= DINP * G4_) return;
    int r = i >> 11, c = i & 2047;
    g_wk1p[i] = (r < 56) ? Wk1[r * G4_ + c] : 0.0f;
}

// ---------------- TF32 GEMM (fp32 A): C[M,2048] = A[M,K] @ W[K,2048] + bias (bf16 out) ----------------
__global__ void __launch_bounds__(256)
k_gemm(const float* __restrict__ A, int lda, int K,
       const float* __restrict__ W, const float* __restrict__ bias,
       __nv_bfloat16* __restrict__ C) {
    __shared__ float As[2][64][36];
    __shared__ float Bs[2][32][72];
    int m0 = blockIdx.x * 64, n0 = blockIdx.y * 64;
    int tid = threadIdx.x;
    int lane = tid & 31, warp = tid >> 5;
    int wm = warp >> 1, wn = warp & 1;
    int g = lane >> 2, tg = lane & 3;

    float acc[4][4];
#pragma unroll
    for (int i = 0; i < 4; i++)
#pragma unroll
        for (int j = 0; j < 4; j++) acc[i][j] = 0.0f;

    int nch = K / KC;
    {
#pragma unroll
        for (int ii = 0; ii < 2; ii++) {
            int idx = tid + 256 * ii;
            int r = idx >> 3, q = idx & 7;
            cpa16(&As[0][r][q * 4], &A[(size_t)(m0 + r) * lda + q * 4]);
        }
#pragma unroll
        for (int ii = 0; ii < 2; ii++) {
            int idx = tid + 256 * ii;
            int k = idx >> 4, q = idx & 15;
            cpa16(&Bs[0][k][q * 4], &W[(size_t)k * G4_ + n0 + q * 4]);
        }
        CP_COMMIT;
    }

    for (int kc = 0; kc < nch; kc++) {
        int b = kc & 1;
        if (kc + 1 < nch) {
            int b2 = b ^ 1;
            int k0 = (kc + 1) * KC;
#pragma unroll
            for (int ii = 0; ii < 2; ii++) {
                int idx = tid + 256 * ii;
                int r = idx >> 3, q = idx & 7;
                cpa16(&As[b2][r][q * 4], &A[(size_t)(m0 + r) * lda + k0 + q * 4]);
            }
#pragma unroll
            for (int ii = 0; ii < 2; ii++) {
                int idx = tid + 256 * ii;
                int k = idx >> 4, q = idx & 15;
                cpa16(&Bs[b2][k][q * 4], &W[(size_t)(k0 + k) * G4_ + n0 + q * 4]);
            }
            CP_COMMIT;
            CP_WAIT1;
        } else {
            CP_WAIT0;
        }
        __syncthreads();
#pragma unroll
        for (int ks = 0; ks < KC; ks += 8) {
            unsigned a0 = f2tf(As[b][wm * 16 + g][ks + tg]);
            unsigned a1 = f2tf(As[b][wm * 16 + g + 8][ks + tg]);
            unsigned a2 = f2tf(As[b][wm * 16 + g][ks + tg + 4]);
            unsigned a3 = f2tf(As[b][wm * 16 + g + 8][ks + tg + 4]);
#pragma unroll
            for (int nt = 0; nt < 4; nt++) {
                unsigned b0 = f2tf(Bs[b][ks + tg][wn * 32 + nt * 8 + g]);
                unsigned b1 = f2tf(Bs[b][ks + tg + 4][wn * 32 + nt * 8 + g]);
                mma8(acc[nt], a0, a1, a2, a3, b0, b1);
            }
        }
        __syncthreads();
    }

    int rl = wm * 16 + g;
#pragma unroll
    for (int nt = 0; nt < 4; nt++) {
        int cl  = wn * 32 + nt * 8 + tg * 2;
        int col = n0 + cl;
        float bb0 = bias[col], bb1 = bias[col + 1];
        size_t o0 = (size_t)(m0 + rl) * G4_ + col;
        size_t o1 = (size_t)(m0 + rl + 8) * G4_ + col;
        __nv_bfloat162 p0 = __floats2bfloat162_rn(acc[nt][0] + bb0, acc[nt][1] + bb1);
        __nv_bfloat162 p1 = __floats2bfloat162_rn(acc[nt][2] + bb0, acc[nt][3] + bb1);
        *reinterpret_cast<__nv_bfloat162*>(C + o0) = p0;
        *reinterpret_cast<__nv_bfloat162*>(C + o1) = p1;
    }
}

// ---------------- TF32 GEMM with bf16 A (layer-2 input projection), K=512, bf16 out ----------------
__global__ void __launch_bounds__(256)
k_gemm_b(const __nv_bfloat16* __restrict__ A,
         const float* __restrict__ W, const float* __restrict__ bias,
         __nv_bfloat16* __restrict__ C) {
    __shared__ __nv_bfloat16 As[2][64][40];
    __shared__ float Bs[2][32][72];
    int m0 = blockIdx.x * 64, n0 = blockIdx.y * 64;
    int tid = threadIdx.x;
    int lane = tid & 31, warp = tid >> 5;
    int wm = warp >> 1, wn = warp & 1;
    int g = lane >> 2, tg = lane & 3;

    float acc[4][4];
#pragma unroll
    for (int i = 0; i < 4; i++)
#pragma unroll
        for (int j = 0; j < 4; j++) acc[i][j] = 0.0f;

    {
        int r = tid >> 2, q = tid & 3;
        cpa16(&As[0][r][q * 8], &A[(size_t)(m0 + r) * H_ + q * 8]);
#pragma unroll
        for (int ii = 0; ii < 2; ii++) {
            int idx = tid + 256 * ii;
            int k = idx >> 4, qq = idx & 15;
            cpa16(&Bs[0][k][qq * 4], &W[(size_t)k * G4_ + n0 + qq * 4]);
        }
        CP_COMMIT;
    }

    for (int kc = 0; kc < 16; kc++) {
        int b = kc & 1;
        if (kc < 15) {
            int b2 = b ^ 1;
            int k0 = (kc + 1) * KC;
            int r = tid >> 2, q = tid & 3;
            cpa16(&As[b2][r][q * 8], &A[(size_t)(m0 + r) * H_ + k0 + q * 8]);
#pragma unroll
            for (int ii = 0; ii < 2; ii++) {
                int idx = tid + 256 * ii;
                int k = idx >> 4, qq = idx & 15;
                cpa16(&Bs[b2][k][qq * 4], &W[(size_t)(k0 + k) * G4_ + n0 + qq * 4]);
            }
            CP_COMMIT;
            CP_WAIT1;
        } else {
            CP_WAIT0;
        }
        __syncthreads();
#pragma unroll
        for (int ks = 0; ks < KC; ks += 8) {
            unsigned a0 = __float_as_uint(__bfloat162float(As[b][wm * 16 + g][ks + tg]));
            unsigned a1 = __float_as_uint(__bfloat162float(As[b][wm * 16 + g + 8][ks + tg]));
            unsigned a2 = __float_as_uint(__bfloat162float(As[b][wm * 16 + g][ks + tg + 4]));
            unsigned a3 = __float_as_uint(__bfloat162float(As[b][wm * 16 + g + 8][ks + tg + 4]));
#pragma unroll
            for (int nt = 0; nt < 4; nt++) {
                unsigned b0 = f2tf(Bs[b][ks + tg][wn * 32 + nt * 8 + g]);
                unsigned b1 = f2tf(Bs[b][ks + tg + 4][wn * 32 + nt * 8 + g]);
                mma8(acc[nt], a0, a1, a2, a3, b0, b1);
            }
        }
        __syncthreads();
    }

    int rl = wm * 16 + g;
#pragma unroll
    for (int nt = 0; nt < 4; nt++) {
        int cl  = wn * 32 + nt * 8 + tg * 2;
        int col = n0 + cl;
        float bb0 = bias[col], bb1 = bias[col + 1];
        size_t o0 = (size_t)(m0 + rl) * G4_ + col;
        size_t o1 = (size_t)(m0 + rl + 8) * G4_ + col;
        __nv_bfloat162 p0 = __floats2bfloat162_rn(acc[nt][0] + bb0, acc[nt][1] + bb1);
        __nv_bfloat162 p1 = __floats2bfloat162_rn(acc[nt][2] + bb0, acc[nt][3] + bb1);
        *reinterpret_cast<__nv_bfloat162*>(C + o0) = p0;
        *reinterpret_cast<__nv_bfloat162*>(C + o1) = p1;
    }
}

// ---------------- persistent bf16 LSTM scan ----------------
// grid (4, 32), 256 threads. CTA: 64 batch rows x 64 z-cols.
// Bs row ns -> z col: gate=(ns>>3)&3, j=(ns>>5)*8+(ns&7); warp wn's 4 acc n8-blocks
// are the 4 gates of the same j range -> cell update fully in registers.
// Whole h tile staged in ONE cp.async burst per step.
__global__ void __launch_bounds__(256)
k_scan(const float* __restrict__ Wr, const __nv_bfloat16* __restrict__ xz,
       __nv_bfloat16* __restrict__ hs, unsigned* __restrict__ ctr) {
    extern __shared__ char smem[];
    __nv_bfloat16* Bsm = reinterpret_cast<__nv_bfloat16*>(smem);
    __nv_bfloat16* Asm = reinterpret_cast<__nv_bfloat16*>(smem + SC_TILE_BYTES);

    int m0 = blockIdx.x * 64;
    int j0 = blockIdx.y * 16;
    int gidx = blockIdx.x;
    int tid = threadIdx.x;
    int lane = tid & 31, warp = tid >> 5;
    int wm = warp >> 1, wn = warp & 1;
    int g = lane >> 2, tg = lane & 3;

    // preload Wr slice: row ns holds column gate*512 + j0 + j
    for (int i = tid; i < 64 * 512; i += 256) {
        int ns = i & 63, k = i >> 6;
        int col = ((ns >> 3) & 3) * 512 + j0 + ((ns >> 5) << 3) + (ns & 7);
        Bsm[ns * NROW + k] = __float2bfloat16(Wr[(size_t)k * G4_ + col]);
    }
    __syncthreads();

    // fragment addressing
    int a_row  = wm * 16 + (lane & 7) + ((lane >> 3) & 1) * 8;
    int a_koff = ((lane >> 4) & 1) * 8;
    int b_nl0  = wn * 32 + ((lane >> 4) & 1) * 8 + (lane & 7);
    int b_koff = ((lane >> 3) & 1) * 8;
    int jloc   = wn * 8 + tg * 2;           // this thread's 2 j's: jloc, jloc+1
    int r0     = m0 + wm * 16 + g;          // rows r0, r0+8

    float creg[4] = {0.0f, 0.0f, 0.0f, 0.0f};   // [rr*2+jj]

    for (int t = 0; t < T_; t++) {
        // stage whole h[t-1] tile (64 x 512 bf16) in one burst
        if (t > 0) {
#pragma unroll
            for (int ii = 0; ii < 16; ii++) {
                int idx = tid + 256 * ii;       // 4096 quads
                int r = idx >> 6, q8 = idx & 63;
                cpa16(&Asm[r * NROW + q8 * 8],
                      &hs[((size_t)(m0 + r) * T_ + (t - 1)) * H_ + q8 * 8]);
            }
            CP_COMMIT;
        }

        // xz for this thread's (2 rows x 4 gates x 2 j's) -> registers (overlaps cp.async)
        float xf[2][4][2];
#pragma unroll
        for (int rr = 0; rr < 2; rr++) {
            const __nv_bfloat16* xp = xz + ((size_t)(r0 + rr * 8) * T_ + t) * G4_ + j0 + jloc;
#pragma unroll
            for (int gate = 0; gate < 4; gate++) {
                __nv_bfloat162 w = *reinterpret_cast<const __nv_bfloat162*>(xp + gate * 512);
                xf[rr][gate][0] = __bfloat162float(w.x);
                xf[rr][gate][1] = __bfloat162float(w.y);
            }
        }

        float acc[4][4];
#pragma unroll
        for (int i = 0; i < 4; i++)
#pragma unroll
            for (int j = 0; j < 4; j++) acc[i][j] = 0.0f;

        if (t > 0) {
            CP_WAIT0;
            __syncthreads();
#pragma unroll 4
            for (int ks = 0; ks < 32; ks++) {
                unsigned a0, a1, a2, a3;
                ldsm4(a0, a1, a2, a3, &Asm[a_row * NROW + ks * 16 + a_koff]);
                unsigned c0, c1, c2, c3;
                ldsm4(c0, c1, c2, c3, &Bsm[b_nl0 * NROW + ks * 16 + b_koff]);
                mma16bf(acc[0], a0, a1, a2, a3, c0, c1);
                mma16bf(acc[1], a0, a1, a2, a3, c2, c3);
                ldsm4(c0, c1, c2, c3, &Bsm[(b_nl0 + 16) * NROW + ks * 16 + b_koff]);
                mma16bf(acc[2], a0, a1, a2, a3, c0, c1);
                mma16bf(acc[3], a0, a1, a2, a3, c2, c3);
            }
        }

        // fused cell update, fully in registers
#pragma unroll
        for (int rr = 0; rr < 2; rr++) {
            float hv[2];
#pragma unroll
            for (int jj = 0; jj < 2; jj++) {
                int q = rr * 2 + jj;
                float zi = acc[0][q] + xf[rr][0][jj];
                float zf = acc[1][q] + xf[rr][1][jj];
                float zg = acc[2][q] + xf[rr][2][jj];
                float zo = acc[3][q] + xf[rr][3][jj];
                float iv = sigm(zi);
                float fv = sigm(zf);
                float gv = tanhf(zg);
                float ov = sigm(zo);
                float cv = fv * creg[q] + iv * gv;
                creg[q] = cv;
                hv[jj] = ov * tanhf(cv);
            }
            *reinterpret_cast<__nv_bfloat162*>(
                hs + ((size_t)(r0 + rr * 8) * T_ + t) * H_ + j0 + jloc) =
                __floats2bfloat162_rn(hv[0], hv[1]);
        }

        // inter-CTA group barrier (32 CTAs share this batch group)
        __threadfence();
        __syncthreads();
        if (tid == 0) {
            atomicAdd(ctr + gidx, 1u);
            unsigned tgt = 32u * (unsigned)(t + 1);
            unsigned v;
            do {
                asm volatile("ld.acquire.gpu.u32 %0, [%1];" : "=r"(v) : "l"(ctr + gidx));
                if (v < tgt) __nanosleep(32);
            } while (v < tgt);
        }
        __syncthreads();
    }
}

// ---------------- output heads: mu, softplus(sigma) (bf16 hs) ----------------
__global__ void k_heads(const __nv_bfloat16* __restrict__ hs,
                        const float* __restrict__ Wmu, const float* __restrict__ bmu,
                        const float* __restrict__ Wsig, const float* __restrict__ bsig,
                        float* __restrict__ out) {
    int wg  = (blockIdx.x * blockDim.x + threadIdx.x) >> 5;
    int lane = threadIdx.x & 31;
    if (wg >= BT_) return;
    const __nv_bfloat16* h = hs + (size_t)wg * H_;
    float smu = 0.0f, ssg = 0.0f;
#pragma unroll 4
    for (int k = lane * 2; k < H_; k += 64) {
        __nv_bfloat162 hh = *reinterpret_cast<const __nv_bfloat162*>(h + k);
        float h0 = __bfloat162float(hh.x), h1 = __bfloat162float(hh.y);
        smu += h0 * Wmu[k] + h1 * Wmu[k + 1];
        ssg += h0 * Wsig[k] + h1 * Wsig[k + 1];
    }
#pragma unroll
    for (int o = 16; o; o >>= 1) {
        smu += __shfl_xor_sync(0xffffffffu, smu, o);
        ssg += __shfl_xor_sync(0xffffffffu, ssg, o);
    }
    if (lane == 0) {
        out[wg] = smu + bmu[0];
        float x = ssg + bsig[0];
        out[BT_ + wg] = (x > 20.0f) ? x : log1pf(expf(x));
    }
}

// ---------------- launch ----------------
extern "C" void kernel_launch(void* const* d_in, const int* in_sizes, int n_in,
                              void* d_out, int out_size) {
    const float* x_cont = (const float*)d_in[0];
    const int*   cat0   = (const int*)  d_in[1];
    const int*   cat1   = (const int*)  d_in[2];
    const float* emb0   = (const float*)d_in[3];
    const float* emb1   = (const float*)d_in[4];
    const float* Wk1    = (const float*)d_in[5];
    const float* Wr1    = (const float*)d_in[6];
    const float* b1     = (const float*)d_in[7];
    const float* Wk2    = (const float*)d_in[8];
    const float* Wr2    = (const float*)d_in[9];
    const float* b2     = (const float*)d_in[10];
    const float* Wmu    = (const float*)d_in[11];
    const float* bmu    = (const float*)d_in[12];
    const float* Wsig   = (const float*)d_in[13];
    const float* bsig   = (const float*)d_in[14];
    float* out = (float*)d_out;

    float *px, *pwk;
    __nv_bfloat16 *pxz, *ph1, *ph2;
    unsigned* pctr;
    cudaGetSymbolAddress((void**)&px,  g_x);
    cudaGetSymbolAddress((void**)&pwk, g_wk1p);
    cudaGetSymbolAddress((void**)&pxz, g_xz);
    cudaGetSymbolAddress((void**)&ph1, g_hs1);
    cudaGetSymbolAddress((void**)&ph2, g_hs2);
    cudaGetSymbolAddress((void**)&pctr, g_ctr);

    cudaFuncSetAttribute(k_scan, cudaFuncAttributeMaxDynamicSharedMemorySize, SC_SMEM);

    dim3 gemm_grid(BT_ / 64, G4_ / 64);   // (768, 32)
    dim3 scan_grid(4, 32);                // 128 persistent CTAs

    k_init<<<1, 32>>>();
    k_build_x<<<(BT_ * DINP + 255) / 256, 256>>>(x_cont, cat0, cat1, emb0, emb1);
    k_padwk<<<(DINP * G4_ + 255) / 256, 256>>>(Wk1);

    // ---- layer 1 ----
    k_gemm<<<gemm_grid, 256>>>(px, DINP, DINP, pwk, b1, pxz);
    k_scan<<<scan_grid, 256, SC_SMEM>>>(Wr1, pxz, ph1, pctr);

    // ---- layer 2 ----
    k_gemm_b<<<gemm_grid, 256>>>(ph1, Wk2, b2, pxz);
    k_scan<<<scan_grid, 256, SC_SMEM>>>(Wr2, pxz, ph2, pctr + 4);

    // ---- heads ----
    k_heads<<<(BT_ * 32 + 255) / 256, 256>>>(ph2, Wmu, bmu, Wsig, bsig, out);
}

// round 6
// speedup vs baseline: 8.2884x; 1.1744x over previous
#include <cuda_runtime.h>
#include <cuda_bf16.h>
#include <math.h>
#include <stdint.h>

// Problem constants
#define B_    256
#define T_    192
#define F_    8
#define E0_   32
#define E1_   16
#define DINP  64          // padded input dim (real 56)
#define H_    512
#define G4_   2048
#define BT_   (B_ * T_)   // 49152
#define KC    32

// Scan smem: Bs [64][520] bf16 + As [64][520] bf16
#define NROW  520
#define SC_TILE_BYTES (64 * NROW * 2)
#define SC_SMEM (2 * SC_TILE_BYTES)

// ---------------- scratch (static device arrays; no allocation) ----------------
__device__ float g_x  [(size_t)BT_ * DINP];            // padded concat input (fp32)
__device__ float g_wk1p[DINP * G4_];                   // padded Wk1
__device__ __nv_bfloat16 g_xz [(size_t)BT_ * G4_];     // input projection (+bias), bf16
__device__ __nv_bfloat16 g_hs1[(size_t)BT_ * H_];      // layer1 hidden outputs (bf16)
__device__ __nv_bfloat16 g_hs2[(size_t)BT_ * H_];      // layer2 hidden outputs (bf16)
__device__ unsigned g_ctr[8];

// ---------------- helpers ----------------
__device__ __forceinline__ unsigned f2tf(float x) {
    unsigned r;
    asm("cvt.rna.tf32.f32 %0, %1;" : "=r"(r) : "f"(x));
    return r;
}

__device__ __forceinline__ void mma8(float* c,
                                     unsigned a0, unsigned a1, unsigned a2, unsigned a3,
                                     unsigned b0, unsigned b1) {
    asm volatile(
        "mma.sync.aligned.m16n8k8.row.col.f32.tf32.tf32.f32 "
        "{%0,%1,%2,%3},{%4,%5,%6,%7},{%8,%9},{%0,%1,%2,%3};\n"
        : "+f"(c[0]), "+f"(c[1]), "+f"(c[2]), "+f"(c[3])
        : "r"(a0), "r"(a1), "r"(a2), "r"(a3), "r"(b0), "r"(b1));
}

__device__ __forceinline__ void mma16bf(float* c,
                                        unsigned a0, unsigned a1, unsigned a2, unsigned a3,
                                        unsigned b0, unsigned b1) {
    asm volatile(
        "mma.sync.aligned.m16n8k16.row.col.f32.bf16.bf16.f32 "
        "{%0,%1,%2,%3},{%4,%5,%6,%7},{%8,%9},{%0,%1,%2,%3};\n"
        : "+f"(c[0]), "+f"(c[1]), "+f"(c[2]), "+f"(c[3])
        : "r"(a0), "r"(a1), "r"(a2), "r"(a3), "r"(b0), "r"(b1));
}

__device__ __forceinline__ void ldsm4(unsigned& r0, unsigned& r1, unsigned& r2, unsigned& r3,
                                      const void* p) {
    unsigned a = (unsigned)__cvta_generic_to_shared(p);
    asm volatile("ldmatrix.sync.aligned.m8n8.x4.shared.b16 {%0,%1,%2,%3}, [%4];"
                 : "=r"(r0), "=r"(r1), "=r"(r2), "=r"(r3) : "r"(a));
}

// fast sigmoid/tanh via MUFU.EX2 path (precision ~1e-6, negligible vs bf16 noise)
__device__ __forceinline__ float sigm(float x) {
    float e = __expf(-x);
    return __fdividef(1.0f, 1.0f + e);
}
__device__ __forceinline__ float tanhfast(float x) {
    float e = __expf(-2.0f * x);
    return __fdividef(2.0f, 1.0f + e) - 1.0f;
}

__device__ __forceinline__ void cpa16(void* dst, const void* src) {
    unsigned d = (unsigned)__cvta_generic_to_shared(dst);
    asm volatile("cp.async.ca.shared.global [%0], [%1], 16;\n" :: "r"(d), "l"(src));
}
#define CP_COMMIT asm volatile("cp.async.commit_group;\n")
#define CP_WAIT0  asm volatile("cp.async.wait_group 0;\n")
#define CP_WAIT1  asm volatile("cp.async.wait_group 1;\n")

// ---------------- tiny kernels ----------------
__global__ void k_init() {
    if (threadIdx.x < 8) g_ctr[threadIdx.x] = 0u;
}

__global__ void k_build_x(const float* __restrict__ xc,
                          const int* __restrict__ c0, const int* __restrict__ c1,
                          const float* __restrict__ e0, const float* __restrict__ e1) {
    int i = blockIdx.x * blockDim.x + threadIdx.x;
    if (i >= BT_ * DINP) return;
    int bt = i >> 6;
    int d  = i & 63;
    float v;
    if (d < F_)                  v = xc[bt * F_ + d];
    else if (d < F_ + E0_)       v = e0[c0[bt] * E0_ + (d - F_)];
    else if (d < F_ + E0_ + E1_) v = e1[c1[bt] * E1_ + (d - F_ - E0_)];
    else                         v = 0.0f;
    g_x[i] = v;
}

__global__ void k_padwk(const float* __restrict__ Wk1) {
    int i = blockIdx.x * blockDim.x + threadIdx.x;
    if (i >= DINP * G4_) return;
    int r = i >> 11, c = i & 2047;
    g_wk1p[i] = (r < 56) ? Wk1[r * G4_ + c] : 0.0f;
}

// ---------------- TF32 GEMM (fp32 A): C[M,2048] = A[M,K] @ W[K,2048] + bias (bf16 out) ----------------
__global__ void __launch_bounds__(256)
k_gemm(const float* __restrict__ A, int lda, int K,
       const float* __restrict__ W, const float* __restrict__ bias,
       __nv_bfloat16* __restrict__ C) {
    __shared__ float As[2][64][36];
    __shared__ float Bs[2][32][72];
    int m0 = blockIdx.x * 64, n0 = blockIdx.y * 64;
    int tid = threadIdx.x;
    int lane = tid & 31, warp = tid >> 5;
    int wm = warp >> 1, wn = warp & 1;
    int g = lane >> 2, tg = lane & 3;

    float acc[4][4];
#pragma unroll
    for (int i = 0; i < 4; i++)
#pragma unroll
        for (int j = 0; j < 4; j++) acc[i][j] = 0.0f;

    int nch = K / KC;
    {
#pragma unroll
        for (int ii = 0; ii < 2; ii++) {
            int idx = tid + 256 * ii;
            int r = idx >> 3, q = idx & 7;
            cpa16(&As[0][r][q * 4], &A[(size_t)(m0 + r) * lda + q * 4]);
        }
#pragma unroll
        for (int ii = 0; ii < 2; ii++) {
            int idx = tid + 256 * ii;
            int k = idx >> 4, q = idx & 15;
            cpa16(&Bs[0][k][q * 4], &W[(size_t)k * G4_ + n0 + q * 4]);
        }
        CP_COMMIT;
    }

    for (int kc = 0; kc < nch; kc++) {
        int b = kc & 1;
        if (kc + 1 < nch) {
            int b2 = b ^ 1;
            int k0 = (kc + 1) * KC;
#pragma unroll
            for (int ii = 0; ii < 2; ii++) {
                int idx = tid + 256 * ii;
                int r = idx >> 3, q = idx & 7;
                cpa16(&As[b2][r][q * 4], &A[(size_t)(m0 + r) * lda + k0 + q * 4]);
            }
#pragma unroll
            for (int ii = 0; ii < 2; ii++) {
                int idx = tid + 256 * ii;
                int k = idx >> 4, q = idx & 15;
                cpa16(&Bs[b2][k][q * 4], &W[(size_t)(k0 + k) * G4_ + n0 + q * 4]);
            }
            CP_COMMIT;
            CP_WAIT1;
        } else {
            CP_WAIT0;
        }
        __syncthreads();
#pragma unroll
        for (int ks = 0; ks < KC; ks += 8) {
            unsigned a0 = f2tf(As[b][wm * 16 + g][ks + tg]);
            unsigned a1 = f2tf(As[b][wm * 16 + g + 8][ks + tg]);
            unsigned a2 = f2tf(As[b][wm * 16 + g][ks + tg + 4]);
            unsigned a3 = f2tf(As[b][wm * 16 + g + 8][ks + tg + 4]);
#pragma unroll
            for (int nt = 0; nt < 4; nt++) {
                unsigned b0 = f2tf(Bs[b][ks + tg][wn * 32 + nt * 8 + g]);
                unsigned b1 = f2tf(Bs[b][ks + tg + 4][wn * 32 + nt * 8 + g]);
                mma8(acc[nt], a0, a1, a2, a3, b0, b1);
            }
        }
        __syncthreads();
    }

    int rl = wm * 16 + g;
#pragma unroll
    for (int nt = 0; nt < 4; nt++) {
        int cl  = wn * 32 + nt * 8 + tg * 2;
        int col = n0 + cl;
        float bb0 = bias[col], bb1 = bias[col + 1];
        size_t o0 = (size_t)(m0 + rl) * G4_ + col;
        size_t o1 = (size_t)(m0 + rl + 8) * G4_ + col;
        __nv_bfloat162 p0 = __floats2bfloat162_rn(acc[nt][0] + bb0, acc[nt][1] + bb1);
        __nv_bfloat162 p1 = __floats2bfloat162_rn(acc[nt][2] + bb0, acc[nt][3] + bb1);
        *reinterpret_cast<__nv_bfloat162*>(C + o0) = p0;
        *reinterpret_cast<__nv_bfloat162*>(C + o1) = p1;
    }
}

// ---------------- TF32 GEMM with bf16 A (layer-2 input projection), K=512, bf16 out ----------------
__global__ void __launch_bounds__(256)
k_gemm_b(const __nv_bfloat16* __restrict__ A,
         const float* __restrict__ W, const float* __restrict__ bias,
         __nv_bfloat16* __restrict__ C) {
    __shared__ __nv_bfloat16 As[2][64][40];
    __shared__ float Bs[2][32][72];
    int m0 = blockIdx.x * 64, n0 = blockIdx.y * 64;
    int tid = threadIdx.x;
    int lane = tid & 31, warp = tid >> 5;
    int wm = warp >> 1, wn = warp & 1;
    int g = lane >> 2, tg = lane & 3;

    float acc[4][4];
#pragma unroll
    for (int i = 0; i < 4; i++)
#pragma unroll
        for (int j = 0; j < 4; j++) acc[i][j] = 0.0f;

    {
        int r = tid >> 2, q = tid & 3;
        cpa16(&As[0][r][q * 8], &A[(size_t)(m0 + r) * H_ + q * 8]);
#pragma unroll
        for (int ii = 0; ii < 2; ii++) {
            int idx = tid + 256 * ii;
            int k = idx >> 4, qq = idx & 15;
            cpa16(&Bs[0][k][qq * 4], &W[(size_t)k * G4_ + n0 + qq * 4]);
        }
        CP_COMMIT;
    }

    for (int kc = 0; kc < 16; kc++) {
        int b = kc & 1;
        if (kc < 15) {
            int b2 = b ^ 1;
            int k0 = (kc + 1) * KC;
            int r = tid >> 2, q = tid & 3;
            cpa16(&As[b2][r][q * 8], &A[(size_t)(m0 + r) * H_ + k0 + q * 8]);
#pragma unroll
            for (int ii = 0; ii < 2; ii++) {
                int idx = tid + 256 * ii;
                int k = idx >> 4, qq = idx & 15;
                cpa16(&Bs[b2][k][qq * 4], &W[(size_t)(k0 + k) * G4_ + n0 + qq * 4]);
            }
            CP_COMMIT;
            CP_WAIT1;
        } else {
            CP_WAIT0;
        }
        __syncthreads();
#pragma unroll
        for (int ks = 0; ks < KC; ks += 8) {
            unsigned a0 = __float_as_uint(__bfloat162float(As[b][wm * 16 + g][ks + tg]));
            unsigned a1 = __float_as_uint(__bfloat162float(As[b][wm * 16 + g + 8][ks + tg]));
            unsigned a2 = __float_as_uint(__bfloat162float(As[b][wm * 16 + g][ks + tg + 4]));
            unsigned a3 = __float_as_uint(__bfloat162float(As[b][wm * 16 + g + 8][ks + tg + 4]));
#pragma unroll
            for (int nt = 0; nt < 4; nt++) {
                unsigned b0 = f2tf(Bs[b][ks + tg][wn * 32 + nt * 8 + g]);
                unsigned b1 = f2tf(Bs[b][ks + tg + 4][wn * 32 + nt * 8 + g]);
                mma8(acc[nt], a0, a1, a2, a3, b0, b1);
            }
        }
        __syncthreads();
    }

    int rl = wm * 16 + g;
#pragma unroll
    for (int nt = 0; nt < 4; nt++) {
        int cl  = wn * 32 + nt * 8 + tg * 2;
        int col = n0 + cl;
        float bb0 = bias[col], bb1 = bias[col + 1];
        size_t o0 = (size_t)(m0 + rl) * G4_ + col;
        size_t o1 = (size_t)(m0 + rl + 8) * G4_ + col;
        __nv_bfloat162 p0 = __floats2bfloat162_rn(acc[nt][0] + bb0, acc[nt][1] + bb1);
        __nv_bfloat162 p1 = __floats2bfloat162_rn(acc[nt][2] + bb0, acc[nt][3] + bb1);
        *reinterpret_cast<__nv_bfloat162*>(C + o0) = p0;
        *reinterpret_cast<__nv_bfloat162*>(C + o1) = p1;
    }
}

// ---------------- persistent bf16 LSTM scan ----------------
// grid (4, 32), 256 threads. CTA: 64 batch rows x 64 z-cols (gate-aligned).
// Changes this round: 2-chunk staged h with mma/load overlap, release-scoped
// barrier arrive (no threadfence), next-step xz prefetch under the spin,
// MUFU-path transcendentals.
__global__ void __launch_bounds__(256)
k_scan(const float* __restrict__ Wr, const __nv_bfloat16* __restrict__ xz,
       __nv_bfloat16* __restrict__ hs, unsigned* __restrict__ ctr) {
    extern __shared__ char smem[];
    __nv_bfloat16* Bsm = reinterpret_cast<__nv_bfloat16*>(smem);
    __nv_bfloat16* Asm = reinterpret_cast<__nv_bfloat16*>(smem + SC_TILE_BYTES);

    int m0 = blockIdx.x * 64;
    int j0 = blockIdx.y * 16;
    int gidx = blockIdx.x;
    int tid = threadIdx.x;
    int lane = tid & 31, warp = tid >> 5;
    int wm = warp >> 1, wn = warp & 1;
    int g = lane >> 2, tg = lane & 3;

    // preload Wr slice: row ns holds column gate*512 + j0 + j
    for (int i = tid; i < 64 * 512; i += 256) {
        int ns = i & 63, k = i >> 6;
        int col = ((ns >> 3) & 3) * 512 + j0 + ((ns >> 5) << 3) + (ns & 7);
        Bsm[ns * NROW + k] = __float2bfloat16(Wr[(size_t)k * G4_ + col]);
    }
    __syncthreads();

    // fragment addressing
    int a_row  = wm * 16 + (lane & 7) + ((lane >> 3) & 1) * 8;
    int a_koff = ((lane >> 4) & 1) * 8;
    int b_nl0  = wn * 32 + ((lane >> 4) & 1) * 8 + (lane & 7);
    int b_koff = ((lane >> 3) & 1) * 8;
    int jloc   = wn * 8 + tg * 2;           // this thread's 2 j's
    int r0     = m0 + wm * 16 + g;          // rows r0, r0+8

    float creg[4] = {0.0f, 0.0f, 0.0f, 0.0f};
    float xf[2][4][2];

    // prologue: xz for t=0
#pragma unroll
    for (int rr = 0; rr < 2; rr++) {
        const __nv_bfloat16* xp = xz + ((size_t)(r0 + rr * 8) * T_) * G4_ + j0 + jloc;
#pragma unroll
        for (int gate = 0; gate < 4; gate++) {
            __nv_bfloat162 w = *reinterpret_cast<const __nv_bfloat162*>(xp + gate * 512);
            xf[rr][gate][0] = __bfloat162float(w.x);
            xf[rr][gate][1] = __bfloat162float(w.y);
        }
    }

    for (int t = 0; t < T_; t++) {
        // stage h[t-1]: two commit groups (k 0..255, k 256..511)
        if (t > 0) {
#pragma unroll
            for (int ii = 0; ii < 8; ii++) {
                int idx = tid + 256 * ii;       // 2048 quads
                int r = idx >> 5, q8 = idx & 31;
                cpa16(&Asm[r * NROW + q8 * 8],
                      &hs[((size_t)(m0 + r) * T_ + (t - 1)) * H_ + q8 * 8]);
            }
            CP_COMMIT;
#pragma unroll
            for (int ii = 0; ii < 8; ii++) {
                int idx = tid + 256 * ii;
                int r = idx >> 5, q8 = (idx & 31) + 32;
                cpa16(&Asm[r * NROW + q8 * 8],
                      &hs[((size_t)(m0 + r) * T_ + (t - 1)) * H_ + q8 * 8]);
            }
            CP_COMMIT;
        }

        float acc[4][4];
#pragma unroll
        for (int i = 0; i < 4; i++)
#pragma unroll
            for (int j = 0; j < 4; j++) acc[i][j] = 0.0f;

        if (t > 0) {
            CP_WAIT1;
            __syncthreads();
#pragma unroll 4
            for (int ks = 0; ks < 16; ks++) {
                unsigned a0, a1, a2, a3;
                ldsm4(a0, a1, a2, a3, &Asm[a_row * NROW + ks * 16 + a_koff]);
                unsigned c0, c1, c2, c3;
                ldsm4(c0, c1, c2, c3, &Bsm[b_nl0 * NROW + ks * 16 + b_koff]);
                mma16bf(acc[0], a0, a1, a2, a3, c0, c1);
                mma16bf(acc[1], a0, a1, a2, a3, c2, c3);
                ldsm4(c0, c1, c2, c3, &Bsm[(b_nl0 + 16) * NROW + ks * 16 + b_koff]);
                mma16bf(acc[2], a0, a1, a2, a3, c0, c1);
                mma16bf(acc[3], a0, a1, a2, a3, c2, c3);
            }
            CP_WAIT0;
            __syncthreads();
#pragma unroll 4
            for (int ks = 16; ks < 32; ks++) {
                unsigned a0, a1, a2, a3;
                ldsm4(a0, a1, a2, a3, &Asm[a_row * NROW + ks * 16 + a_koff]);
                unsigned c0, c1, c2, c3;
                ldsm4(c0, c1, c2, c3, &Bsm[b_nl0 * NROW + ks * 16 + b_koff]);
                mma16bf(acc[0], a0, a1, a2, a3, c0, c1);
                mma16bf(acc[1], a0, a1, a2, a3, c2, c3);
                ldsm4(c0, c1, c2, c3, &Bsm[(b_nl0 + 16) * NROW + ks * 16 + b_koff]);
                mma16bf(acc[2], a0, a1, a2, a3, c0, c1);
                mma16bf(acc[3], a0, a1, a2, a3, c2, c3);
            }
        }

        // fused cell update, fully in registers
#pragma unroll
        for (int rr = 0; rr < 2; rr++) {
            float hv[2];
#pragma unroll
            for (int jj = 0; jj < 2; jj++) {
                int q = rr * 2 + jj;
                float zi = acc[0][q] + xf[rr][0][jj];
                float zf = acc[1][q] + xf[rr][1][jj];
                float zg = acc[2][q] + xf[rr][2][jj];
                float zo = acc[3][q] + xf[rr][3][jj];
                float iv = sigm(zi);
                float fv = sigm(zf);
                float gv = tanhfast(zg);
                float ov = sigm(zo);
                float cv = fv * creg[q] + iv * gv;
                creg[q] = cv;
                hv[jj] = ov * tanhfast(cv);
            }
            *reinterpret_cast<__nv_bfloat162*>(
                hs + ((size_t)(r0 + rr * 8) * T_ + t) * H_ + j0 + jloc) =
                __floats2bfloat162_rn(hv[0], hv[1]);
        }

        // group barrier: release-scoped arrive by tid0 (after cta barrier)
        __syncthreads();
        if (tid == 0)
            asm volatile("red.release.gpu.global.add.u32 [%0], %1;"
                         :: "l"(ctr + gidx), "r"(1u) : "memory");

        // prefetch next step's xz while others arrive (xf dead after update)
        if (t + 1 < T_) {
#pragma unroll
            for (int rr = 0; rr < 2; rr++) {
                const __nv_bfloat16* xp =
                    xz + ((size_t)(r0 + rr * 8) * T_ + (t + 1)) * G4_ + j0 + jloc;
#pragma unroll
                for (int gate = 0; gate < 4; gate++) {
                    __nv_bfloat162 w = *reinterpret_cast<const __nv_bfloat162*>(xp + gate * 512);
                    xf[rr][gate][0] = __bfloat162float(w.x);
                    xf[rr][gate][1] = __bfloat162float(w.y);
                }
            }
        }

        if (tid == 0) {
            unsigned tgt = 32u * (unsigned)(t + 1);
            unsigned v;
            do {
                asm volatile("ld.acquire.gpu.u32 %0, [%1];" : "=r"(v) : "l"(ctr + gidx));
            } while (v < tgt);
        }
        __syncthreads();
    }
}

// ---------------- output heads: mu, softplus(sigma) (bf16 hs) ----------------
__global__ void k_heads(const __nv_bfloat16* __restrict__ hs,
                        const float* __restrict__ Wmu, const float* __restrict__ bmu,
                        const float* __restrict__ Wsig, const float* __restrict__ bsig,
                        float* __restrict__ out) {
    int wg  = (blockIdx.x * blockDim.x + threadIdx.x) >> 5;
    int lane = threadIdx.x & 31;
    if (wg >= BT_) return;
    const __nv_bfloat16* h = hs + (size_t)wg * H_;
    float smu = 0.0f, ssg = 0.0f;
#pragma unroll 4
    for (int k = lane * 2; k < H_; k += 64) {
        __nv_bfloat162 hh = *reinterpret_cast<const __nv_bfloat162*>(h + k);
        float h0 = __bfloat162float(hh.x), h1 = __bfloat162float(hh.y);
        smu += h0 * Wmu[k] + h1 * Wmu[k + 1];
        ssg += h0 * Wsig[k] + h1 * Wsig[k + 1];
    }
#pragma unroll
    for (int o = 16; o; o >>= 1) {
        smu += __shfl_xor_sync(0xffffffffu, smu, o);
        ssg += __shfl_xor_sync(0xffffffffu, ssg, o);
    }
    if (lane == 0) {
        out[wg] = smu + bmu[0];
        float x = ssg + bsig[0];
        out[BT_ + wg] = (x > 20.0f) ? x : log1pf(expf(x));
    }
}

// ---------------- launch ----------------
extern "C" void kernel_launch(void* const* d_in, const int* in_sizes, int n_in,
                              void* d_out, int out_size) {
    const float* x_cont = (const float*)d_in[0];
    const int*   cat0   = (const int*)  d_in[1];
    const int*   cat1   = (const int*)  d_in[2];
    const float* emb0   = (const float*)d_in[3];
    const float* emb1   = (const float*)d_in[4];
    const float* Wk1    = (const float*)d_in[5];
    const float* Wr1    = (const float*)d_in[6];
    const float* b1     = (const float*)d_in[7];
    const float* Wk2    = (const float*)d_in[8];
    const float* Wr2    = (const float*)d_in[9];
    const float* b2     = (const float*)d_in[10];
    const float* Wmu    = (const float*)d_in[11];
    const float* bmu    = (const float*)d_in[12];
    const float* Wsig   = (const float*)d_in[13];
    const float* bsig   = (const float*)d_in[14];
    float* out = (float*)d_out;

    float *px, *pwk;
    __nv_bfloat16 *pxz, *ph1, *ph2;
    unsigned* pctr;
    cudaGetSymbolAddress((void**)&px,  g_x);
    cudaGetSymbolAddress((void**)&pwk, g_wk1p);
    cudaGetSymbolAddress((void**)&pxz, g_xz);
    cudaGetSymbolAddress((void**)&ph1, g_hs1);
    cudaGetSymbolAddress((void**)&ph2, g_hs2);
    cudaGetSymbolAddress((void**)&pctr, g_ctr);

    cudaFuncSetAttribute(k_scan, cudaFuncAttributeMaxDynamicSharedMemorySize, SC_SMEM);

    dim3 gemm_grid(BT_ / 64, G4_ / 64);   // (768, 32)
    dim3 scan_grid(4, 32);                // 128 persistent CTAs

    k_init<<<1, 32>>>();
    k_build_x<<<(BT_ * DINP + 255) / 256, 256>>>(x_cont, cat0, cat1, emb0, emb1);
    k_padwk<<<(DINP * G4_ + 255) / 256, 256>>>(Wk1);

    // ---- layer 1 ----
    k_gemm<<<gemm_grid, 256>>>(px, DINP, DINP, pwk, b1, pxz);
    k_scan<<<scan_grid, 256, SC_SMEM>>>(Wr1, pxz, ph1, pctr);

    // ---- layer 2 ----
    k_gemm_b<<<gemm_grid, 256>>>(ph1, Wk2, b2, pxz);
    k_scan<<<scan_grid, 256, SC_SMEM>>>(Wr2, pxz, ph2, pctr + 4);

    // ---- heads ----
    k_heads<<<(BT_ * 32 + 255) / 256, 256>>>(ph2, Wmu, bmu, Wsig, bsig, out);
}